// round 13
// baseline (speedup 1.0000x reference)
#include <cuda_runtime.h>
#include <cuda_bf16.h>
#include <stdint.h>
#include <math.h>

#define BQ  4
#define SEQ 1024
#define DM  1024
#define NH  16
#define HD  64

// ---------------- scratch (no allocations allowed) ----------------
__device__ float g_attn[BQ * NH * SEQ * SEQ];  // fallback if attn not an output
__device__ uint32_t g_mbits[BQ * SEQ * (SEQ / 32)];

__device__ __nv_bfloat16 g_q_hi[BQ * SEQ * DM],  g_q_lo[BQ * SEQ * DM];
__device__ __nv_bfloat16 g_k_hi[BQ * SEQ * DM],  g_k_lo[BQ * SEQ * DM];
__device__ __nv_bfloat16 g_v_hi[BQ * SEQ * DM],  g_v_lo[BQ * SEQ * DM];
__device__ __nv_bfloat16 g_qp_hi[BQ * SEQ * DM], g_qp_lo[BQ * SEQ * DM];
__device__ __nv_bfloat16 g_kp_hi[BQ * SEQ * DM], g_kp_lo[BQ * SEQ * DM];
__device__ __nv_bfloat16 g_vp_hi[BQ * SEQ * DM], g_vp_lo[BQ * SEQ * DM];
__device__ __nv_bfloat16 g_c_hi[BQ * SEQ * DM],  g_c_lo[BQ * SEQ * DM];
__device__ __nv_bfloat16 g_wq_hi[DM * DM], g_wq_lo[DM * DM];
__device__ __nv_bfloat16 g_wk_hi[DM * DM], g_wk_lo[DM * DM];
__device__ __nv_bfloat16 g_wv_hi[DM * DM], g_wv_lo[DM * DM];
__device__ __nv_bfloat16 g_wd_hi[DM * DM], g_wd_lo[DM * DM];

#define SWZ(o)   ((o) ^ (((o) >> 3) & 0x70))              // 128B rows
#define SWZ32(o) ((o) ^ ((((o) >> 7) & 3) << 4))          // 64B rows

__device__ __forceinline__ uint32_t smem_u32(const void* p) {
    uint32_t a;
    asm("{ .reg .u64 t; cvta.to.shared.u64 t, %1; cvt.u32.u64 %0, t; }" : "=r"(a) : "l"(p));
    return a;
}
__device__ __forceinline__ void ldm_x4(uint32_t* r, uint32_t addr) {
    asm volatile("ldmatrix.sync.aligned.m8n8.x4.shared.b16 {%0,%1,%2,%3}, [%4];"
        : "=r"(r[0]), "=r"(r[1]), "=r"(r[2]), "=r"(r[3]) : "r"(addr));
}
__device__ __forceinline__ void ldm_x4t(uint32_t* r, uint32_t addr) {
    asm volatile("ldmatrix.sync.aligned.m8n8.x4.trans.shared.b16 {%0,%1,%2,%3}, [%4];"
        : "=r"(r[0]), "=r"(r[1]), "=r"(r[2]), "=r"(r[3]) : "r"(addr));
}
__device__ __forceinline__ void mma_bf16(float* d, const uint32_t* a, const uint32_t* b) {
    asm volatile(
        "mma.sync.aligned.m16n8k16.row.col.f32.bf16.bf16.f32 "
        "{%0,%1,%2,%3}, {%4,%5,%6,%7}, {%8,%9}, {%0,%1,%2,%3};"
        : "+f"(d[0]), "+f"(d[1]), "+f"(d[2]), "+f"(d[3])
        : "r"(a[0]), "r"(a[1]), "r"(a[2]), "r"(a[3]), "r"(b[0]), "r"(b[1]));
}
#define CP16(dst, src) asm volatile("cp.async.cg.shared.global [%0], [%1], 16;" :: "r"(dst), "l"(src))
#define CP_COMMIT()    asm volatile("cp.async.commit_group;" ::: "memory")
#define CP_WAIT0()     asm volatile("cp.async.wait_group 0;" ::: "memory")
#define CP_WAIT1()     asm volatile("cp.async.wait_group 1;" ::: "memory")
#define CP_WAIT2()     asm volatile("cp.async.wait_group 2;" ::: "memory")

__device__ __forceinline__ uint32_t pack_bf2(float x, float y) {
    __nv_bfloat162 t(__float2bfloat16_rn(x), __float2bfloat16_rn(y));
    return *(uint32_t*)&t;
}

// ---------------------------------------------------------------------------
// prep: all converts + mask bit-packing in ONE launch. (unchanged)
// ---------------------------------------------------------------------------
__device__ __forceinline__ void split_store(
    const float* __restrict__ x, __nv_bfloat16* hi, __nv_bfloat16* lo, int i)
{
    float4 v = ((const float4*)x)[i];
    __nv_bfloat16 h0 = __float2bfloat16_rn(v.x);
    __nv_bfloat16 h1 = __float2bfloat16_rn(v.y);
    __nv_bfloat16 h2 = __float2bfloat16_rn(v.z);
    __nv_bfloat16 h3 = __float2bfloat16_rn(v.w);
    __nv_bfloat16 l0 = __float2bfloat16_rn(v.x - __bfloat162float(h0));
    __nv_bfloat16 l1 = __float2bfloat16_rn(v.y - __bfloat162float(h1));
    __nv_bfloat16 l2 = __float2bfloat16_rn(v.z - __bfloat162float(h2));
    __nv_bfloat16 l3 = __float2bfloat16_rn(v.w - __bfloat162float(h3));
    __nv_bfloat162* hp = (__nv_bfloat162*)(hi + (size_t)i * 4);
    __nv_bfloat162* lp = (__nv_bfloat162*)(lo + (size_t)i * 4);
    hp[0] = __nv_bfloat162(h0, h1); hp[1] = __nv_bfloat162(h2, h3);
    lp[0] = __nv_bfloat162(l0, l1); lp[1] = __nv_bfloat162(l2, l3);
}

__global__ __launch_bounds__(256) void prep(
    const float* __restrict__ q, const float* __restrict__ k,
    const float* __restrict__ v,
    const float* __restrict__ Wq, const float* __restrict__ Wk,
    const float* __restrict__ Wv, const float* __restrict__ Wd,
    const int* __restrict__ mask, uint32_t* __restrict__ bits)
{
    int bid = blockIdx.x;
    if (bid < 12288) {
        int z = bid >> 12;
        int i = (bid & 4095) * 256 + threadIdx.x;
        if (z == 0)      split_store(q, g_q_hi, g_q_lo, i);
        else if (z == 1) split_store(k, g_k_hi, g_k_lo, i);
        else             split_store(v, g_v_hi, g_v_lo, i);
    } else if (bid < 16384) {
        int r = bid - 12288;
        int z = r >> 10;
        int i = (r & 1023) * 256 + threadIdx.x;
        if (z == 0)      split_store(Wq, g_wq_hi, g_wq_lo, i);
        else if (z == 1) split_store(Wk, g_wk_hi, g_wk_lo, i);
        else if (z == 2) split_store(Wv, g_wv_hi, g_wv_lo, i);
        else             split_store(Wd, g_wd_hi, g_wd_lo, i);
    } else {
        int wdx = (bid - 16384) * 256 + threadIdx.x;
        const int* p = mask + (size_t)wdx * 32;
        uint32_t word = 0;
        #pragma unroll
        for (int j = 0; j < 8; j++) {
            int4 mv = ((const int4*)p)[j];
            word |= (mv.x ? 1u : 0u) << (j * 4 + 0);
            word |= (mv.y ? 1u : 0u) << (j * 4 + 1);
            word |= (mv.z ? 1u : 0u) << (j * 4 + 2);
            word |= (mv.w ? 1u : 0u) << (j * 4 + 3);
        }
        bits[wdx] = word;
    }
}

// ---------------------------------------------------------------------------
// GEMM body (unchanged): BK=32, 3-stage cp.async, 2 CTAs/SM.
// ---------------------------------------------------------------------------
#define GEMM_SMEM (3 * 32768)

__device__ __forceinline__ void gemm_body(
    const __nv_bfloat16* __restrict__ Ahi, const __nv_bfloat16* __restrict__ Alo,
    const __nv_bfloat16* __restrict__ Whi, const __nv_bfloat16* __restrict__ Wlo,
    const float* __restrict__ bias, float* __restrict__ Cf32,
    __nv_bfloat16* __restrict__ Chi, __nv_bfloat16* __restrict__ Clo,
    char* sm)
{
    const int K = DM, N = DM;

    int tid = threadIdx.x, w = tid >> 5, l = tid & 31;
    int m0 = blockIdx.y * 128, n0 = blockIdx.x * 128;
    int wm = w & 1, wn = w >> 1;

    uint32_t sb = smem_u32(sm);

    int a_row = wm * 64 + (l & 15);
    int a_cb  = (l >> 4) * 16;
    int b_row = wn * 32 + (l & 7) + ((l >> 4) * 8);
    int b_cb  = ((l >> 3) & 1) * 16;

    float acc[4][4][4] = {};
    const int NK = K / 32;

    auto load_stage = [&](int s, int kc) {
        uint32_t base = sb + (uint32_t)s * 32768;
        #pragma unroll
        for (int it = 0; it < 2; it++) {
            int idx = tid + it * 256;
            int row = idx >> 2, c = idx & 3;
            size_t ga = (size_t)(m0 + row) * K + kc * 32 + c * 8;
            size_t gw = (size_t)(n0 + row) * K + kc * 32 + c * 8;
            uint32_t so = SWZ32(row * 64 + c * 16);
            CP16(base +     0 + so, Ahi + ga);
            CP16(base +  8192 + so, Alo + ga);
            CP16(base + 16384 + so, Whi + gw);
            CP16(base + 24576 + so, Wlo + gw);
        }
        CP_COMMIT();
    };

    load_stage(0, 0);
    load_stage(1, 1);

    for (int kc = 0; kc < NK; kc++) {
        __syncthreads();
        if (kc + 2 < NK) { load_stage((kc + 2) % 3, kc + 2); CP_WAIT2(); }
        else if (kc + 1 < NK) { CP_WAIT1(); }
        else { CP_WAIT0(); }
        __syncthreads();

        uint32_t st = sb + (uint32_t)(kc % 3) * 32768;
        #pragma unroll
        for (int kk = 0; kk < 2; kk++) {
            int ks2 = kk * 32;
            uint32_t ah[4][4], al[4][4], bw[2][4];
            #pragma unroll
            for (int mf = 0; mf < 4; mf++) {
                uint32_t off = SWZ32((a_row + mf * 16) * 64 + ks2 + a_cb);
                ldm_x4(ah[mf], st + 0 + off);
                ldm_x4(al[mf], st + 8192 + off);
            }
            #pragma unroll
            for (int bp = 0; bp < 2; bp++) {
                uint32_t off = SWZ32((b_row + bp * 16) * 64 + ks2 + b_cb);
                ldm_x4(bw[bp], st + 16384 + off);
            }
            #pragma unroll
            for (int mf = 0; mf < 4; mf++)
                #pragma unroll
                for (int nf = 0; nf < 4; nf++)
                    mma_bf16(acc[mf][nf], ah[mf], &bw[nf >> 1][(nf & 1) * 2]);
            #pragma unroll
            for (int mf = 0; mf < 4; mf++)
                #pragma unroll
                for (int nf = 0; nf < 4; nf++)
                    mma_bf16(acc[mf][nf], al[mf], &bw[nf >> 1][(nf & 1) * 2]);
            #pragma unroll
            for (int bp = 0; bp < 2; bp++) {
                uint32_t off = SWZ32((b_row + bp * 16) * 64 + ks2 + b_cb);
                ldm_x4(bw[bp], st + 24576 + off);
            }
            #pragma unroll
            for (int mf = 0; mf < 4; mf++)
                #pragma unroll
                for (int nf = 0; nf < 4; nf++)
                    mma_bf16(acc[mf][nf], ah[mf], &bw[nf >> 1][(nf & 1) * 2]);
        }
    }

    int er = l >> 2, ec = (l & 3) * 2;
    #pragma unroll
    for (int mf = 0; mf < 4; mf++) {
        #pragma unroll
        for (int nf = 0; nf < 4; nf++) {
            int gm = m0 + wm * 64 + mf * 16 + er;
            int gn = n0 + wn * 32 + nf * 8 + ec;
            if (Cf32) {
                float b0 = bias ? bias[gn] : 0.0f;
                float b1 = bias ? bias[gn + 1] : 0.0f;
                float2 v0, v1;
                v0.x = acc[mf][nf][0] + b0; v0.y = acc[mf][nf][1] + b1;
                v1.x = acc[mf][nf][2] + b0; v1.y = acc[mf][nf][3] + b1;
                *(float2*)&Cf32[(size_t)gm * N + gn]       = v0;
                *(float2*)&Cf32[(size_t)(gm + 8) * N + gn] = v1;
            } else {
                #pragma unroll
                for (int rr = 0; rr < 2; rr++) {
                    float vx = acc[mf][nf][rr * 2], vy = acc[mf][nf][rr * 2 + 1];
                    float hx = __bfloat162float(__float2bfloat16_rn(vx));
                    float hy = __bfloat162float(__float2bfloat16_rn(vy));
                    size_t o = (size_t)(gm + rr * 8) * N + gn;
                    *(uint32_t*)&Chi[o] = pack_bf2(vx, vy);
                    *(uint32_t*)&Clo[o] = pack_bf2(vx - hx, vy - hy);
                }
            }
        }
    }
}

__global__ __launch_bounds__(256, 2) void qkv_gemm()
{
    extern __shared__ char sm[];
    int z = blockIdx.z;
    if (z == 0)
        gemm_body(g_q_hi, g_q_lo, g_wq_hi, g_wq_lo, nullptr, nullptr, g_qp_hi, g_qp_lo, sm);
    else if (z == 1)
        gemm_body(g_k_hi, g_k_lo, g_wk_hi, g_wk_lo, nullptr, nullptr, g_kp_hi, g_kp_lo, sm);
    else
        gemm_body(g_v_hi, g_v_lo, g_wv_hi, g_wv_lo, nullptr, nullptr, g_vp_hi, g_vp_lo, sm);
}

__global__ __launch_bounds__(256, 2) void out_gemm(const float* __restrict__ bias,
                                                   float* __restrict__ out)
{
    extern __shared__ char sm[];
    gemm_body(g_c_hi, g_c_lo, g_wd_hi, g_wd_lo, bias, out, nullptr, nullptr, sm);
}

// ---------------------------------------------------------------------------
// Fused attention (single kernel): 64-row CTAs, 256 threads, 2 CTAs/SM.
// Sweep 1: K-only tiles, online (max,sum) in regs; smem stats reduce.
// Sweep 2: K+V tiles; P = exp(s-m)/sum; attn write; ctx = P@V.
// smem: Q 16K | KV stages 2x32K | stats 1.5K
// ---------------------------------------------------------------------------
#define PA_SMEM (16384 + 65536 + 1536)

__global__ __launch_bounds__(256, 2) void attn_fused(float* __restrict__ attn)
{
    extern __shared__ char sm[];
    const uint32_t O_Q = 0, O_KV = 16384, O_ST = 81920;

    int tid = threadIdx.x, w = tid >> 5, l = tid & 31;
    int bh = blockIdx.y, b = bh >> 4, h = bh & 15;
    int m0 = blockIdx.x * 64;
    int wm = w & 3, wn = w >> 2;
    uint32_t sb = smem_u32(sm);

    const __nv_bfloat16* Qh = g_qp_hi + (size_t)b * SEQ * DM + h * HD;
    const __nv_bfloat16* Ql = g_qp_lo + (size_t)b * SEQ * DM + h * HD;
    const __nv_bfloat16* Kh = g_kp_hi + (size_t)b * SEQ * DM + h * HD;
    const __nv_bfloat16* Kl = g_kp_lo + (size_t)b * SEQ * DM + h * HD;
    const __nv_bfloat16* Vh = g_vp_hi + (size_t)b * SEQ * DM + h * HD;
    const __nv_bfloat16* Vl = g_vp_lo + (size_t)b * SEQ * DM + h * HD;
    const uint32_t* mrow_bits = g_mbits + ((size_t)b * SEQ) * 32;

    auto load_k = [&](int nt) {
        uint32_t base = sb + O_KV + (uint32_t)(nt & 1) * 32768;
        #pragma unroll
        for (int it = 0; it < 2; it++) {
            int idx = tid + it * 256;
            int row = idx >> 3, c = idx & 7;
            uint32_t so = SWZ(row * 128 + c * 16);
            size_t g = (size_t)(nt * 64 + row) * DM + c * 8;
            CP16(base + so,        Kh + g);
            CP16(base + 8192 + so, Kl + g);
        }
        CP_COMMIT();
    };
    auto load_kv = [&](int nt) {
        uint32_t base = sb + O_KV + (uint32_t)(nt & 1) * 32768;
        #pragma unroll
        for (int it = 0; it < 2; it++) {
            int idx = tid + it * 256;
            int row = idx >> 3, c = idx & 7;
            uint32_t so = SWZ(row * 128 + c * 16);
            size_t g = (size_t)(nt * 64 + row) * DM + c * 8;
            CP16(base + so,         Kh + g);
            CP16(base +  8192 + so, Kl + g);
            CP16(base + 16384 + so, Vh + g);
            CP16(base + 24576 + so, Vl + g);
        }
        CP_COMMIT();
    };

    // Q tile (persistent): 64 rows
    #pragma unroll
    for (int it = 0; it < 2; it++) {
        int idx = tid + it * 256;
        int row = idx >> 3, c = idx & 7;
        uint32_t so = SWZ(row * 128 + c * 16);
        size_t g = (size_t)(m0 + row) * DM + c * 8;
        *(uint4*)(sm + O_Q + so)        = *(const uint4*)(Qh + g);
        *(uint4*)(sm + O_Q + 8192 + so) = *(const uint4*)(Ql + g);
    }
    load_k(0);

    const float scale = 0.03125f;
    int er = l >> 2, ec = (l & 3) * 2;

    // ---------------- sweep 1: online stats ----------------
    float mrun[2] = {-1e30f, -1e30f};
    float srun[2] = {};

    for (int nt = 0; nt < 16; nt++) {
        if (nt + 1 < 16) { load_k(nt + 1); CP_WAIT1(); }
        else             { CP_WAIT0(); }
        __syncthreads();

        uint32_t kst = sb + O_KV + (uint32_t)(nt & 1) * 32768;

        float acc[4][4] = {};
        #pragma unroll
        for (int kk = 0; kk < 4; kk++) {
            int ks2 = kk * 32;
            uint32_t ah[4], al[4], bwh[2][4], bwl[2][4];
            {
                uint32_t off = SWZ((wm * 16 + (l & 15)) * 128 + ks2 + (l >> 4) * 16);
                ldm_x4(ah, sb + O_Q + off);
                ldm_x4(al, sb + O_Q + 8192 + off);
            }
            #pragma unroll
            for (int bp = 0; bp < 2; bp++) {
                uint32_t off = SWZ((wn * 32 + bp * 16 + (l & 7) + ((l >> 4) * 8)) * 128
                                   + ks2 + ((l >> 3) & 1) * 16);
                ldm_x4(bwh[bp], kst + off);
                ldm_x4(bwl[bp], kst + 8192 + off);
            }
            #pragma unroll
            for (int nf = 0; nf < 4; nf++) {
                mma_bf16(acc[nf], ah, &bwh[nf >> 1][(nf & 1) * 2]);
                mma_bf16(acc[nf], al, &bwh[nf >> 1][(nf & 1) * 2]);
                mma_bf16(acc[nf], ah, &bwl[nf >> 1][(nf & 1) * 2]);
            }
        }

        #pragma unroll
        for (int rr = 0; rr < 2; rr++) {
            int rl = wm * 16 + rr * 8 + er;
            uint32_t word = mrow_bits[(size_t)(m0 + rl) * 32 + nt * 2 + wn];
            float v[8];
            float tmax = -1e30f;
            #pragma unroll
            for (int nf = 0; nf < 4; nf++) {
                int sh = nf * 8 + ec;
                float m0f = ((word >> sh) & 1u) ? -1e9f : 0.0f;
                float m1f = ((word >> (sh + 1)) & 1u) ? -1e9f : 0.0f;
                v[nf * 2]     = acc[nf][rr * 2]     * scale + m0f;
                v[nf * 2 + 1] = acc[nf][rr * 2 + 1] * scale + m1f;
                tmax = fmaxf(tmax, fmaxf(v[nf * 2], v[nf * 2 + 1]));
            }
            tmax = fmaxf(tmax, __shfl_xor_sync(0xffffffffu, tmax, 1));
            tmax = fmaxf(tmax, __shfl_xor_sync(0xffffffffu, tmax, 2));
            float nm = fmaxf(mrun[rr], tmax);
            float ts = 0.0f;
            #pragma unroll
            for (int i = 0; i < 8; i++) ts += __expf(v[i] - nm);
            ts += __shfl_xor_sync(0xffffffffu, ts, 1);
            ts += __shfl_xor_sync(0xffffffffu, ts, 2);
            srun[rr] = srun[rr] * __expf(mrun[rr] - nm) + ts;
            mrun[rr] = nm;
        }
        __syncthreads();
    }

    // kick off first sweep-2 load to overlap stats reduction
    load_kv(0);

    // ---------------- stats reduce across wn ----------------
    float* sm_m  = (float*)(sm + O_ST);        // 128
    float* sm_s  = sm_m + 128;                 // 128
    float* sm_fm = sm_s + 128;                 // 64  (final max)
    float* sm_fi = sm_fm + 64;                 // 64  (final 1/sum)
    if ((l & 3) == 0) {
        #pragma unroll
        for (int rr = 0; rr < 2; rr++) {
            int rl = wm * 16 + rr * 8 + er;
            sm_m[wn * 64 + rl] = mrun[rr];
            sm_s[wn * 64 + rl] = srun[rr];
        }
    }
    __syncthreads();
    if (tid < 64) {
        float ma = sm_m[tid], mb2 = sm_m[64 + tid];
        float m = fmaxf(ma, mb2);
        float s = sm_s[tid] * __expf(ma - m) + sm_s[64 + tid] * __expf(mb2 - m);
        sm_fm[tid] = m;
        sm_fi[tid] = __frcp_rn(s);
    }
    __syncthreads();

    float rmax[2], rinv[2];
    #pragma unroll
    for (int rr = 0; rr < 2; rr++) {
        int rl = wm * 16 + rr * 8 + er;
        rmax[rr] = sm_fm[rl];
        rinv[rr] = sm_fi[rl];
    }

    // ---------------- sweep 2: P + attn write + ctx ----------------
    float ctx[8][4] = {};

    for (int nt = 0; nt < 16; nt++) {
        if (nt + 1 < 16) { load_kv(nt + 1); CP_WAIT1(); }
        else             { CP_WAIT0(); }
        __syncthreads();

        uint32_t kst = sb + O_KV + (uint32_t)(nt & 1) * 32768;

        float acc[4][4] = {};
        #pragma unroll
        for (int kk = 0; kk < 4; kk++) {
            int ks2 = kk * 32;
            uint32_t ah[4], al[4], bwh[2][4], bwl[2][4];
            {
                uint32_t off = SWZ((wm * 16 + (l & 15)) * 128 + ks2 + (l >> 4) * 16);
                ldm_x4(ah, sb + O_Q + off);
                ldm_x4(al, sb + O_Q + 8192 + off);
            }
            #pragma unroll
            for (int bp = 0; bp < 2; bp++) {
                uint32_t off = SWZ((wn * 32 + bp * 16 + (l & 7) + ((l >> 4) * 8)) * 128
                                   + ks2 + ((l >> 3) & 1) * 16);
                ldm_x4(bwh[bp], kst + off);
                ldm_x4(bwl[bp], kst + 8192 + off);
            }
            #pragma unroll
            for (int nf = 0; nf < 4; nf++) {
                mma_bf16(acc[nf], ah, &bwh[nf >> 1][(nf & 1) * 2]);
                mma_bf16(acc[nf], al, &bwh[nf >> 1][(nf & 1) * 2]);
                mma_bf16(acc[nf], ah, &bwl[nf >> 1][(nf & 1) * 2]);
            }
        }

        // P = exp(s - m) * rinv; write attn; keep P in acc
        #pragma unroll
        for (int rr = 0; rr < 2; rr++) {
            int rl = wm * 16 + rr * 8 + er;
            int gm = m0 + rl;
            uint32_t word = mrow_bits[(size_t)gm * 32 + nt * 2 + wn];
            #pragma unroll
            for (int nf = 0; nf < 4; nf++) {
                int sh = nf * 8 + ec;
                float m0f = ((word >> sh) & 1u) ? -1e9f : 0.0f;
                float m1f = ((word >> (sh + 1)) & 1u) ? -1e9f : 0.0f;
                float sv0 = acc[nf][rr * 2]     * scale + m0f;
                float sv1 = acc[nf][rr * 2 + 1] * scale + m1f;
                float2 pv;
                pv.x = __expf(sv0 - rmax[rr]) * rinv[rr];
                pv.y = __expf(sv1 - rmax[rr]) * rinv[rr];
                int gn = nt * 64 + wn * 32 + nf * 8 + ec;
                *(float2*)&attn[((size_t)bh * SEQ + gm) * SEQ + gn] = pv;
                acc[nf][rr * 2]     = pv.x;
                acc[nf][rr * 2 + 1] = pv.y;
            }
        }

        // ctx += P @ V (this warp's 32 keys)
        #pragma unroll
        for (int kk = 0; kk < 2; kk++) {
            uint32_t pah[4], pal[4], bvh[4][4], bvl[4][4];
            {
                float* a0 = acc[kk * 2];
                float* a1 = acc[kk * 2 + 1];
                pah[0] = pack_bf2(a0[0], a0[1]);
                pah[1] = pack_bf2(a0[2], a0[3]);
                pah[2] = pack_bf2(a1[0], a1[1]);
                pah[3] = pack_bf2(a1[2], a1[3]);
                float h00 = __bfloat162float(__float2bfloat16_rn(a0[0]));
                float h01 = __bfloat162float(__float2bfloat16_rn(a0[1]));
                float h02 = __bfloat162float(__float2bfloat16_rn(a0[2]));
                float h03 = __bfloat162float(__float2bfloat16_rn(a0[3]));
                float h10 = __bfloat162float(__float2bfloat16_rn(a1[0]));
                float h11 = __bfloat162float(__float2bfloat16_rn(a1[1]));
                float h12 = __bfloat162float(__float2bfloat16_rn(a1[2]));
                float h13 = __bfloat162float(__float2bfloat16_rn(a1[3]));
                pal[0] = pack_bf2(a0[0] - h00, a0[1] - h01);
                pal[1] = pack_bf2(a0[2] - h02, a0[3] - h03);
                pal[2] = pack_bf2(a1[0] - h10, a1[1] - h11);
                pal[3] = pack_bf2(a1[2] - h12, a1[3] - h13);
            }
            #pragma unroll
            for (int nb = 0; nb < 4; nb++) {
                uint32_t off = SWZ((wn * 32 + kk * 16 + (l & 15)) * 128
                                   + (nb * 16 + (l >> 4) * 8) * 2);
                ldm_x4t(bvh[nb], kst + 16384 + off);
                ldm_x4t(bvl[nb], kst + 24576 + off);
            }
            #pragma unroll
            for (int nd = 0; nd < 8; nd++) {
                mma_bf16(ctx[nd], pah, &bvh[nd >> 1][(nd & 1) * 2]);
                mma_bf16(ctx[nd], pal, &bvh[nd >> 1][(nd & 1) * 2]);
                mma_bf16(ctx[nd], pah, &bvl[nd >> 1][(nd & 1) * 2]);
            }
        }
        __syncthreads();
    }

    // cross-wn reduce via smem (alias KV stage 0), write ctx bf16 hi/lo
    float* red = (float*)(sm + O_KV);   // 64 x 64 fp32 = 16KB
    if (wn == 1) {
        #pragma unroll
        for (int nd = 0; nd < 8; nd++)
            #pragma unroll
            for (int rr = 0; rr < 2; rr++) {
                int row = wm * 16 + rr * 8 + er;
                float2 v;
                v.x = ctx[nd][rr * 2];
                v.y = ctx[nd][rr * 2 + 1];
                *(float2*)&red[row * 64 + nd * 8 + ec] = v;
            }
    }
    __syncthreads();
    if (wn == 0) {
        __nv_bfloat16* Chi = g_c_hi + (size_t)b * SEQ * DM + h * HD;
        __nv_bfloat16* Clo = g_c_lo + (size_t)b * SEQ * DM + h * HD;
        #pragma unroll
        for (int nd = 0; nd < 8; nd++)
            #pragma unroll
            for (int rr = 0; rr < 2; rr++) {
                int row = wm * 16 + rr * 8 + er;
                int col = nd * 8 + ec;
                float2 o = *(float2*)&red[row * 64 + col];
                float vx = ctx[nd][rr * 2] + o.x;
                float vy = ctx[nd][rr * 2 + 1] + o.y;
                float hx = __bfloat162float(__float2bfloat16_rn(vx));
                float hy = __bfloat162float(__float2bfloat16_rn(vy));
                size_t off = (size_t)(m0 + row) * DM + col;
                *(uint32_t*)&Chi[off] = pack_bf2(vx, vy);
                *(uint32_t*)&Clo[off] = pack_bf2(vx - hx, vy - hy);
            }
    }
}

// ---------------------------------------------------------------------------
extern "C" void kernel_launch(void* const* d_in, const int* in_sizes, int n_in,
                              void* d_out, int out_size)
{
    const float* q   = (const float*)d_in[0];
    const float* k   = (const float*)d_in[1];
    const float* v   = (const float*)d_in[2];
    const int*  mask = (const int*)d_in[3];
    const float* Wq  = (const float*)d_in[4];
    const float* Wk  = (const float*)d_in[5];
    const float* Wv  = (const float*)d_in[6];
    const float* Wd  = (const float*)d_in[7];
    const float* bd  = (const float*)d_in[8];
    float* out = (float*)d_out;

    const long long out_elems  = (long long)BQ * SEQ * DM;
    const long long attn_elems = (long long)BQ * NH * SEQ * SEQ;
    float* attn;
    if ((long long)out_size >= out_elems + attn_elems) {
        attn = out + out_elems;
    } else {
        cudaGetSymbolAddress((void**)&attn, g_attn);
    }

    cudaFuncSetAttribute(qkv_gemm,   cudaFuncAttributeMaxDynamicSharedMemorySize, GEMM_SMEM);
    cudaFuncSetAttribute(out_gemm,   cudaFuncAttributeMaxDynamicSharedMemorySize, GEMM_SMEM);
    cudaFuncSetAttribute(attn_fused, cudaFuncAttributeMaxDynamicSharedMemorySize, PA_SMEM);

    uint32_t* mb;
    cudaGetSymbolAddress((void**)&mb, g_mbits);

    prep<<<16896, 256>>>(q, k, v, Wq, Wk, Wv, Wd, mask, mb);

    qkv_gemm<<<dim3(DM / 128, (BQ * SEQ) / 128, 3), 256, GEMM_SMEM>>>();

    attn_fused<<<dim3(SEQ / 64, BQ * NH), 256, PA_SMEM>>>(attn);

    out_gemm<<<dim3(DM / 128, (BQ * SEQ) / 128), 256, GEMM_SMEM>>>(bd, out);
}

// round 14
// speedup vs baseline: 1.0208x; 1.0208x over previous
#include <cuda_runtime.h>
#include <cuda_bf16.h>
#include <stdint.h>
#include <math.h>

#define BQ  4
#define SEQ 1024
#define DM  1024
#define NH  16
#define HD  64

// ---------------- scratch (no allocations allowed) ----------------
__device__ float g_attn[BQ * NH * SEQ * SEQ];  // fallback if attn not an output
__device__ float g_rmax[BQ * NH * SEQ];
__device__ float g_rsum[BQ * NH * SEQ];
__device__ uint32_t g_mbits[BQ * SEQ * (SEQ / 32)];

__device__ __nv_bfloat16 g_q_hi[BQ * SEQ * DM],  g_q_lo[BQ * SEQ * DM];
__device__ __nv_bfloat16 g_k_hi[BQ * SEQ * DM],  g_k_lo[BQ * SEQ * DM];
__device__ __nv_bfloat16 g_v_hi[BQ * SEQ * DM],  g_v_lo[BQ * SEQ * DM];
__device__ __nv_bfloat16 g_qp_hi[BQ * SEQ * DM], g_qp_lo[BQ * SEQ * DM];
__device__ __nv_bfloat16 g_kp_hi[BQ * SEQ * DM], g_kp_lo[BQ * SEQ * DM];
__device__ __nv_bfloat16 g_vp_hi[BQ * SEQ * DM], g_vp_lo[BQ * SEQ * DM];
__device__ __nv_bfloat16 g_c_hi[BQ * SEQ * DM],  g_c_lo[BQ * SEQ * DM];
__device__ __nv_bfloat16 g_wq_hi[DM * DM], g_wq_lo[DM * DM];
__device__ __nv_bfloat16 g_wk_hi[DM * DM], g_wk_lo[DM * DM];
__device__ __nv_bfloat16 g_wv_hi[DM * DM], g_wv_lo[DM * DM];
__device__ __nv_bfloat16 g_wd_hi[DM * DM], g_wd_lo[DM * DM];

#define SWZ(o)   ((o) ^ (((o) >> 3) & 0x70))              // 128B rows
#define SWZ32(o) ((o) ^ ((((o) >> 7) & 3) << 4))          // 64B rows

__device__ __forceinline__ uint32_t smem_u32(const void* p) {
    uint32_t a;
    asm("{ .reg .u64 t; cvta.to.shared.u64 t, %1; cvt.u32.u64 %0, t; }" : "=r"(a) : "l"(p));
    return a;
}
__device__ __forceinline__ void ldm_x4(uint32_t* r, uint32_t addr) {
    asm volatile("ldmatrix.sync.aligned.m8n8.x4.shared.b16 {%0,%1,%2,%3}, [%4];"
        : "=r"(r[0]), "=r"(r[1]), "=r"(r[2]), "=r"(r[3]) : "r"(addr));
}
__device__ __forceinline__ void ldm_x4t(uint32_t* r, uint32_t addr) {
    asm volatile("ldmatrix.sync.aligned.m8n8.x4.trans.shared.b16 {%0,%1,%2,%3}, [%4];"
        : "=r"(r[0]), "=r"(r[1]), "=r"(r[2]), "=r"(r[3]) : "r"(addr));
}
__device__ __forceinline__ void mma_bf16(float* d, const uint32_t* a, const uint32_t* b) {
    asm volatile(
        "mma.sync.aligned.m16n8k16.row.col.f32.bf16.bf16.f32 "
        "{%0,%1,%2,%3}, {%4,%5,%6,%7}, {%8,%9}, {%0,%1,%2,%3};"
        : "+f"(d[0]), "+f"(d[1]), "+f"(d[2]), "+f"(d[3])
        : "r"(a[0]), "r"(a[1]), "r"(a[2]), "r"(a[3]), "r"(b[0]), "r"(b[1]));
}
#define CP16(dst, src) asm volatile("cp.async.cg.shared.global [%0], [%1], 16;" :: "r"(dst), "l"(src))
#define CP_COMMIT()    asm volatile("cp.async.commit_group;" ::: "memory")
#define CP_WAIT0()     asm volatile("cp.async.wait_group 0;" ::: "memory")
#define CP_WAIT1()     asm volatile("cp.async.wait_group 1;" ::: "memory")
#define CP_WAIT2()     asm volatile("cp.async.wait_group 2;" ::: "memory")

__device__ __forceinline__ uint32_t pack_bf2(float x, float y) {
    __nv_bfloat162 t(__float2bfloat16_rn(x), __float2bfloat16_rn(y));
    return *(uint32_t*)&t;
}

// ---------------------------------------------------------------------------
// prep: converts ONLY (mask packing moved into qkv_gemm launch).
// ---------------------------------------------------------------------------
__device__ __forceinline__ void split_store(
    const float* __restrict__ x, __nv_bfloat16* hi, __nv_bfloat16* lo, int i)
{
    float4 v = ((const float4*)x)[i];
    __nv_bfloat16 h0 = __float2bfloat16_rn(v.x);
    __nv_bfloat16 h1 = __float2bfloat16_rn(v.y);
    __nv_bfloat16 h2 = __float2bfloat16_rn(v.z);
    __nv_bfloat16 h3 = __float2bfloat16_rn(v.w);
    __nv_bfloat16 l0 = __float2bfloat16_rn(v.x - __bfloat162float(h0));
    __nv_bfloat16 l1 = __float2bfloat16_rn(v.y - __bfloat162float(h1));
    __nv_bfloat16 l2 = __float2bfloat16_rn(v.z - __bfloat162float(h2));
    __nv_bfloat16 l3 = __float2bfloat16_rn(v.w - __bfloat162float(h3));
    __nv_bfloat162* hp = (__nv_bfloat162*)(hi + (size_t)i * 4);
    __nv_bfloat162* lp = (__nv_bfloat162*)(lo + (size_t)i * 4);
    hp[0] = __nv_bfloat162(h0, h1); hp[1] = __nv_bfloat162(h2, h3);
    lp[0] = __nv_bfloat162(l0, l1); lp[1] = __nv_bfloat162(l2, l3);
}

__global__ __launch_bounds__(256) void prep(
    const float* __restrict__ q, const float* __restrict__ k,
    const float* __restrict__ v,
    const float* __restrict__ Wq, const float* __restrict__ Wk,
    const float* __restrict__ Wv, const float* __restrict__ Wd)
{
    int bid = blockIdx.x;
    if (bid < 12288) {
        int z = bid >> 12;
        int i = (bid & 4095) * 256 + threadIdx.x;
        if (z == 0)      split_store(q, g_q_hi, g_q_lo, i);
        else if (z == 1) split_store(k, g_k_hi, g_k_lo, i);
        else             split_store(v, g_v_hi, g_v_lo, i);
    } else {
        int r = bid - 12288;
        int z = r >> 10;
        int i = (r & 1023) * 256 + threadIdx.x;
        if (z == 0)      split_store(Wq, g_wq_hi, g_wq_lo, i);
        else if (z == 1) split_store(Wk, g_wk_hi, g_wk_lo, i);
        else if (z == 2) split_store(Wv, g_wv_hi, g_wv_lo, i);
        else             split_store(Wd, g_wd_hi, g_wd_lo, i);
    }
}

// ---------------------------------------------------------------------------
// GEMM body (unchanged): BK=32, 3-stage cp.async, 2 CTAs/SM.
// ---------------------------------------------------------------------------
#define GEMM_SMEM (3 * 32768)

__device__ __forceinline__ void gemm_body(
    const __nv_bfloat16* __restrict__ Ahi, const __nv_bfloat16* __restrict__ Alo,
    const __nv_bfloat16* __restrict__ Whi, const __nv_bfloat16* __restrict__ Wlo,
    const float* __restrict__ bias, float* __restrict__ Cf32,
    __nv_bfloat16* __restrict__ Chi, __nv_bfloat16* __restrict__ Clo,
    char* sm)
{
    const int K = DM, N = DM;

    int tid = threadIdx.x, w = tid >> 5, l = tid & 31;
    int m0 = blockIdx.y * 128, n0 = blockIdx.x * 128;
    int wm = w & 1, wn = w >> 1;

    uint32_t sb = smem_u32(sm);

    int a_row = wm * 64 + (l & 15);
    int a_cb  = (l >> 4) * 16;
    int b_row = wn * 32 + (l & 7) + ((l >> 4) * 8);
    int b_cb  = ((l >> 3) & 1) * 16;

    float acc[4][4][4] = {};
    const int NK = K / 32;

    auto load_stage = [&](int s, int kc) {
        uint32_t base = sb + (uint32_t)s * 32768;
        #pragma unroll
        for (int it = 0; it < 2; it++) {
            int idx = tid + it * 256;
            int row = idx >> 2, c = idx & 3;
            size_t ga = (size_t)(m0 + row) * K + kc * 32 + c * 8;
            size_t gw = (size_t)(n0 + row) * K + kc * 32 + c * 8;
            uint32_t so = SWZ32(row * 64 + c * 16);
            CP16(base +     0 + so, Ahi + ga);
            CP16(base +  8192 + so, Alo + ga);
            CP16(base + 16384 + so, Whi + gw);
            CP16(base + 24576 + so, Wlo + gw);
        }
        CP_COMMIT();
    };

    load_stage(0, 0);
    load_stage(1, 1);

    for (int kc = 0; kc < NK; kc++) {
        __syncthreads();
        if (kc + 2 < NK) { load_stage((kc + 2) % 3, kc + 2); CP_WAIT2(); }
        else if (kc + 1 < NK) { CP_WAIT1(); }
        else { CP_WAIT0(); }
        __syncthreads();

        uint32_t st = sb + (uint32_t)(kc % 3) * 32768;
        #pragma unroll
        for (int kk = 0; kk < 2; kk++) {
            int ks2 = kk * 32;
            uint32_t ah[4][4], al[4][4], bw[2][4];
            #pragma unroll
            for (int mf = 0; mf < 4; mf++) {
                uint32_t off = SWZ32((a_row + mf * 16) * 64 + ks2 + a_cb);
                ldm_x4(ah[mf], st + 0 + off);
                ldm_x4(al[mf], st + 8192 + off);
            }
            #pragma unroll
            for (int bp = 0; bp < 2; bp++) {
                uint32_t off = SWZ32((b_row + bp * 16) * 64 + ks2 + b_cb);
                ldm_x4(bw[bp], st + 16384 + off);
            }
            #pragma unroll
            for (int mf = 0; mf < 4; mf++)
                #pragma unroll
                for (int nf = 0; nf < 4; nf++)
                    mma_bf16(acc[mf][nf], ah[mf], &bw[nf >> 1][(nf & 1) * 2]);
            #pragma unroll
            for (int mf = 0; mf < 4; mf++)
                #pragma unroll
                for (int nf = 0; nf < 4; nf++)
                    mma_bf16(acc[mf][nf], al[mf], &bw[nf >> 1][(nf & 1) * 2]);
            #pragma unroll
            for (int bp = 0; bp < 2; bp++) {
                uint32_t off = SWZ32((b_row + bp * 16) * 64 + ks2 + b_cb);
                ldm_x4(bw[bp], st + 24576 + off);
            }
            #pragma unroll
            for (int mf = 0; mf < 4; mf++)
                #pragma unroll
                for (int nf = 0; nf < 4; nf++)
                    mma_bf16(acc[mf][nf], ah[mf], &bw[nf >> 1][(nf & 1) * 2]);
        }
    }

    int er = l >> 2, ec = (l & 3) * 2;
    #pragma unroll
    for (int mf = 0; mf < 4; mf++) {
        #pragma unroll
        for (int nf = 0; nf < 4; nf++) {
            int gm = m0 + wm * 64 + mf * 16 + er;
            int gn = n0 + wn * 32 + nf * 8 + ec;
            if (Cf32) {
                float b0 = bias ? bias[gn] : 0.0f;
                float b1 = bias ? bias[gn + 1] : 0.0f;
                float2 v0, v1;
                v0.x = acc[mf][nf][0] + b0; v0.y = acc[mf][nf][1] + b1;
                v1.x = acc[mf][nf][2] + b0; v1.y = acc[mf][nf][3] + b1;
                *(float2*)&Cf32[(size_t)gm * N + gn]       = v0;
                *(float2*)&Cf32[(size_t)(gm + 8) * N + gn] = v1;
            } else {
                #pragma unroll
                for (int rr = 0; rr < 2; rr++) {
                    float vx = acc[mf][nf][rr * 2], vy = acc[mf][nf][rr * 2 + 1];
                    float hx = __bfloat162float(__float2bfloat16_rn(vx));
                    float hy = __bfloat162float(__float2bfloat16_rn(vy));
                    size_t o = (size_t)(gm + rr * 8) * N + gn;
                    *(uint32_t*)&Chi[o] = pack_bf2(vx, vy);
                    *(uint32_t*)&Clo[o] = pack_bf2(vx - hx, vy - hy);
                }
            }
        }
    }
}

// z = 0..2: Q/K/V projections. z = 3: mask bit-packing (hides the 256MB
// int32 mask read under the tensor-bound GEMM CTAs).
__global__ __launch_bounds__(256, 2) void qkv_gemm(
    const int* __restrict__ mask, uint32_t* __restrict__ bits)
{
    extern __shared__ char sm[];
    int z = blockIdx.z;
    if (z == 0)
        gemm_body(g_q_hi, g_q_lo, g_wq_hi, g_wq_lo, nullptr, nullptr, g_qp_hi, g_qp_lo, sm);
    else if (z == 1)
        gemm_body(g_k_hi, g_k_lo, g_wk_hi, g_wk_lo, nullptr, nullptr, g_kp_hi, g_kp_lo, sm);
    else if (z == 2)
        gemm_body(g_v_hi, g_v_lo, g_wv_hi, g_wv_lo, nullptr, nullptr, g_vp_hi, g_vp_lo, sm);
    else {
        // 256 CTAs x 256 threads x 2 words = 131072 mask words
        int flat = (blockIdx.y * gridDim.x + blockIdx.x) * 256 + threadIdx.x;
        #pragma unroll
        for (int t = 0; t < 2; t++) {
            int wdx = flat * 2 + t;
            const int* p = mask + (size_t)wdx * 32;
            uint32_t word = 0;
            #pragma unroll
            for (int j = 0; j < 8; j++) {
                int4 mv = ((const int4*)p)[j];
                word |= (mv.x ? 1u : 0u) << (j * 4 + 0);
                word |= (mv.y ? 1u : 0u) << (j * 4 + 1);
                word |= (mv.z ? 1u : 0u) << (j * 4 + 2);
                word |= (mv.w ? 1u : 0u) << (j * 4 + 3);
            }
            bits[wdx] = word;
        }
    }
}

__global__ __launch_bounds__(256, 2) void out_gemm(const float* __restrict__ bias,
                                                   float* __restrict__ out)
{
    extern __shared__ char sm[];
    gemm_body(g_c_hi, g_c_lo, g_wd_hi, g_wd_lo, bias, out, nullptr, nullptr, sm);
}

// ---------------------------------------------------------------------------
// Fused attention, pass 1 (R12): 64-row CTAs, 256 threads, 64-key
// double-buffered tiles. wm=w&3 (16 rows), wn=w>>2 (32-key half). 4 CTAs/SM.
// ---------------------------------------------------------------------------
#define P1_SMEM (16384 + 32768 + 1024)

__global__ __launch_bounds__(256, 4) void attn_pass1()
{
    extern __shared__ char sm[];
    const uint32_t O_Q = 0, O_K = 16384, O_MS = 49152;

    int tid = threadIdx.x, w = tid >> 5, l = tid & 31;
    int bh = blockIdx.y, b = bh >> 4, h = bh & 15;
    int m0 = blockIdx.x * 64;
    int wm = w & 3, wn = w >> 2;
    uint32_t sb = smem_u32(sm);
    float* sm_m = (float*)(sm + O_MS);     // 2 x 64
    float* sm_s = sm_m + 128;

    const __nv_bfloat16* Qh = g_qp_hi + (size_t)b * SEQ * DM + h * HD;
    const __nv_bfloat16* Ql = g_qp_lo + (size_t)b * SEQ * DM + h * HD;
    const __nv_bfloat16* Kh = g_kp_hi + (size_t)b * SEQ * DM + h * HD;
    const __nv_bfloat16* Kl = g_kp_lo + (size_t)b * SEQ * DM + h * HD;
    const uint32_t* mrow_bits = g_mbits + ((size_t)b * SEQ) * 32;

    auto load_k = [&](int nt) {
        uint32_t base = sb + O_K + (uint32_t)(nt & 1) * 16384;
        #pragma unroll
        for (int it = 0; it < 2; it++) {
            int idx = tid + it * 256;
            int row = idx >> 3, c = idx & 7;
            uint32_t so = SWZ(row * 128 + c * 16);
            size_t g = (size_t)(nt * 64 + row) * DM + c * 8;
            CP16(base + so,        Kh + g);
            CP16(base + 8192 + so, Kl + g);
        }
        CP_COMMIT();
    };

    #pragma unroll
    for (int it = 0; it < 2; it++) {
        int idx = tid + it * 256;
        int row = idx >> 3, c = idx & 7;
        uint32_t so = SWZ(row * 128 + c * 16);
        size_t g = (size_t)(m0 + row) * DM + c * 8;
        *(uint4*)(sm + O_Q + so)        = *(const uint4*)(Qh + g);
        *(uint4*)(sm + O_Q + 8192 + so) = *(const uint4*)(Ql + g);
    }
    load_k(0);

    float mrun[2] = {-1e30f, -1e30f};
    float srun[2] = {};
    const float scale = 0.03125f;
    int er = l >> 2, ec = (l & 3) * 2;

    for (int nt = 0; nt < 16; nt++) {
        if (nt + 1 < 16) { load_k(nt + 1); CP_WAIT1(); }
        else             { CP_WAIT0(); }
        __syncthreads();

        uint32_t kst = sb + O_K + (uint32_t)(nt & 1) * 16384;

        float acc[4][4] = {};
        #pragma unroll
        for (int kk = 0; kk < 4; kk++) {
            int ks2 = kk * 32;
            uint32_t ah[4], al[4], bwh[2][4], bwl[2][4];
            {
                uint32_t off = SWZ((wm * 16 + (l & 15)) * 128 + ks2 + (l >> 4) * 16);
                ldm_x4(ah, sb + O_Q + off);
                ldm_x4(al, sb + O_Q + 8192 + off);
            }
            #pragma unroll
            for (int bp = 0; bp < 2; bp++) {
                uint32_t off = SWZ((wn * 32 + bp * 16 + (l & 7) + ((l >> 4) * 8)) * 128
                                   + ks2 + ((l >> 3) & 1) * 16);
                ldm_x4(bwh[bp], kst + off);
                ldm_x4(bwl[bp], kst + 8192 + off);
            }
            #pragma unroll
            for (int nf = 0; nf < 4; nf++) {
                mma_bf16(acc[nf], ah, &bwh[nf >> 1][(nf & 1) * 2]);
                mma_bf16(acc[nf], al, &bwh[nf >> 1][(nf & 1) * 2]);
                mma_bf16(acc[nf], ah, &bwl[nf >> 1][(nf & 1) * 2]);
            }
        }

        #pragma unroll
        for (int rr = 0; rr < 2; rr++) {
            int rl = wm * 16 + rr * 8 + er;
            uint32_t word = mrow_bits[(size_t)(m0 + rl) * 32 + nt * 2 + wn];
            float v[8];
            float tmax = -1e30f;
            #pragma unroll
            for (int nf = 0; nf < 4; nf++) {
                int sh = nf * 8 + ec;
                float m0f = ((word >> sh) & 1u) ? -1e9f : 0.0f;
                float m1f = ((word >> (sh + 1)) & 1u) ? -1e9f : 0.0f;
                v[nf * 2]     = acc[nf][rr * 2]     * scale + m0f;
                v[nf * 2 + 1] = acc[nf][rr * 2 + 1] * scale + m1f;
                tmax = fmaxf(tmax, fmaxf(v[nf * 2], v[nf * 2 + 1]));
            }
            tmax = fmaxf(tmax, __shfl_xor_sync(0xffffffffu, tmax, 1));
            tmax = fmaxf(tmax, __shfl_xor_sync(0xffffffffu, tmax, 2));
            float nm = fmaxf(mrun[rr], tmax);
            float ts = 0.0f;
            #pragma unroll
            for (int i = 0; i < 8; i++) ts += __expf(v[i] - nm);
            ts += __shfl_xor_sync(0xffffffffu, ts, 1);
            ts += __shfl_xor_sync(0xffffffffu, ts, 2);
            srun[rr] = srun[rr] * __expf(mrun[rr] - nm) + ts;
            mrun[rr] = nm;
        }
        __syncthreads();
    }

    if ((l & 3) == 0) {
        #pragma unroll
        for (int rr = 0; rr < 2; rr++) {
            int rl = wm * 16 + rr * 8 + er;
            sm_m[wn * 64 + rl] = mrun[rr];
            sm_s[wn * 64 + rl] = srun[rr];
        }
    }
    __syncthreads();
    if (tid < 64) {
        float ma = sm_m[tid], mb2 = sm_m[64 + tid];
        float m = fmaxf(ma, mb2);
        float s = sm_s[tid] * __expf(ma - m) + sm_s[64 + tid] * __expf(mb2 - m);
        g_rmax[(size_t)bh * SEQ + m0 + tid] = m;
        g_rsum[(size_t)bh * SEQ + m0 + tid] = s;
    }
}

// ---------------------------------------------------------------------------
// Fused attention, pass 2 (R12): 64-row CTAs, 64-key double-buffered tiles,
// 2 CTAs/SM.
// ---------------------------------------------------------------------------
#define P2_SMEM (16384 + 65536)

__global__ __launch_bounds__(256, 2) void attn_pass2(float* __restrict__ attn)
{
    extern __shared__ char sm[];
    const uint32_t O_Q = 0, O_KV = 16384;

    int tid = threadIdx.x, w = tid >> 5, l = tid & 31;
    int bh = blockIdx.y, b = bh >> 4, h = bh & 15;
    int m0 = blockIdx.x * 64;
    int wm = w & 3, wn = w >> 2;
    uint32_t sb = smem_u32(sm);

    const __nv_bfloat16* Qh = g_qp_hi + (size_t)b * SEQ * DM + h * HD;
    const __nv_bfloat16* Ql = g_qp_lo + (size_t)b * SEQ * DM + h * HD;
    const __nv_bfloat16* Kh = g_kp_hi + (size_t)b * SEQ * DM + h * HD;
    const __nv_bfloat16* Kl = g_kp_lo + (size_t)b * SEQ * DM + h * HD;
    const __nv_bfloat16* Vh = g_vp_hi + (size_t)b * SEQ * DM + h * HD;
    const __nv_bfloat16* Vl = g_vp_lo + (size_t)b * SEQ * DM + h * HD;
    const uint32_t* mrow_bits = g_mbits + ((size_t)b * SEQ) * 32;

    auto load_kv = [&](int nt) {
        uint32_t base = sb + O_KV + (uint32_t)(nt & 1) * 32768;
        #pragma unroll
        for (int it = 0; it < 2; it++) {
            int idx = tid + it * 256;
            int row = idx >> 3, c = idx & 7;
            uint32_t so = SWZ(row * 128 + c * 16);
            size_t g = (size_t)(nt * 64 + row) * DM + c * 8;
            CP16(base + so,         Kh + g);
            CP16(base +  8192 + so, Kl + g);
            CP16(base + 16384 + so, Vh + g);
            CP16(base + 24576 + so, Vl + g);
        }
        CP_COMMIT();
    };

    #pragma unroll
    for (int it = 0; it < 2; it++) {
        int idx = tid + it * 256;
        int row = idx >> 3, c = idx & 7;
        uint32_t so = SWZ(row * 128 + c * 16);
        size_t g = (size_t)(m0 + row) * DM + c * 8;
        *(uint4*)(sm + O_Q + so)        = *(const uint4*)(Qh + g);
        *(uint4*)(sm + O_Q + 8192 + so) = *(const uint4*)(Ql + g);
    }
    load_kv(0);

    int er = l >> 2, ec = (l & 3) * 2;
    const float scale = 0.03125f;

    float rmax[2], rinv[2];
    #pragma unroll
    for (int rr = 0; rr < 2; rr++) {
        int gm = m0 + wm * 16 + rr * 8 + er;
        rmax[rr] = g_rmax[(size_t)bh * SEQ + gm];
        rinv[rr] = __frcp_rn(g_rsum[(size_t)bh * SEQ + gm]);
    }

    float ctx[8][4] = {};

    for (int nt = 0; nt < 16; nt++) {
        if (nt + 1 < 16) { load_kv(nt + 1); CP_WAIT1(); }
        else             { CP_WAIT0(); }
        __syncthreads();

        uint32_t kst = sb + O_KV + (uint32_t)(nt & 1) * 32768;

        float acc[4][4] = {};
        #pragma unroll
        for (int kk = 0; kk < 4; kk++) {
            int ks2 = kk * 32;
            uint32_t ah[4], al[4], bwh[2][4], bwl[2][4];
            {
                uint32_t off = SWZ((wm * 16 + (l & 15)) * 128 + ks2 + (l >> 4) * 16);
                ldm_x4(ah, sb + O_Q + off);
                ldm_x4(al, sb + O_Q + 8192 + off);
            }
            #pragma unroll
            for (int bp = 0; bp < 2; bp++) {
                uint32_t off = SWZ((wn * 32 + bp * 16 + (l & 7) + ((l >> 4) * 8)) * 128
                                   + ks2 + ((l >> 3) & 1) * 16);
                ldm_x4(bwh[bp], kst + off);
                ldm_x4(bwl[bp], kst + 8192 + off);
            }
            #pragma unroll
            for (int nf = 0; nf < 4; nf++) {
                mma_bf16(acc[nf], ah, &bwh[nf >> 1][(nf & 1) * 2]);
                mma_bf16(acc[nf], al, &bwh[nf >> 1][(nf & 1) * 2]);
                mma_bf16(acc[nf], ah, &bwl[nf >> 1][(nf & 1) * 2]);
            }
        }

        // P = exp(s - m) * rinv; write attn; keep P in acc
        #pragma unroll
        for (int rr = 0; rr < 2; rr++) {
            int rl = wm * 16 + rr * 8 + er;
            int gm = m0 + rl;
            uint32_t word = mrow_bits[(size_t)gm * 32 + nt * 2 + wn];
            #pragma unroll
            for (int nf = 0; nf < 4; nf++) {
                int sh = nf * 8 + ec;
                float m0f = ((word >> sh) & 1u) ? -1e9f : 0.0f;
                float m1f = ((word >> (sh + 1)) & 1u) ? -1e9f : 0.0f;
                float sv0 = acc[nf][rr * 2]     * scale + m0f;
                float sv1 = acc[nf][rr * 2 + 1] * scale + m1f;
                float2 pv;
                pv.x = __expf(sv0 - rmax[rr]) * rinv[rr];
                pv.y = __expf(sv1 - rmax[rr]) * rinv[rr];
                int gn = nt * 64 + wn * 32 + nf * 8 + ec;
                *(float2*)&attn[((size_t)bh * SEQ + gm) * SEQ + gn] = pv;
                acc[nf][rr * 2]     = pv.x;
                acc[nf][rr * 2 + 1] = pv.y;
            }
        }

        // ctx += P @ V (this warp's 32 keys)
        #pragma unroll
        for (int kk = 0; kk < 2; kk++) {
            uint32_t pah[4], pal[4], bvh[4][4], bvl[4][4];
            {
                float* a0 = acc[kk * 2];
                float* a1 = acc[kk * 2 + 1];
                pah[0] = pack_bf2(a0[0], a0[1]);
                pah[1] = pack_bf2(a0[2], a0[3]);
                pah[2] = pack_bf2(a1[0], a1[1]);
                pah[3] = pack_bf2(a1[2], a1[3]);
                float h00 = __bfloat162float(__float2bfloat16_rn(a0[0]));
                float h01 = __bfloat162float(__float2bfloat16_rn(a0[1]));
                float h02 = __bfloat162float(__float2bfloat16_rn(a0[2]));
                float h03 = __bfloat162float(__float2bfloat16_rn(a0[3]));
                float h10 = __bfloat162float(__float2bfloat16_rn(a1[0]));
                float h11 = __bfloat162float(__float2bfloat16_rn(a1[1]));
                float h12 = __bfloat162float(__float2bfloat16_rn(a1[2]));
                float h13 = __bfloat162float(__float2bfloat16_rn(a1[3]));
                pal[0] = pack_bf2(a0[0] - h00, a0[1] - h01);
                pal[1] = pack_bf2(a0[2] - h02, a0[3] - h03);
                pal[2] = pack_bf2(a1[0] - h10, a1[1] - h11);
                pal[3] = pack_bf2(a1[2] - h12, a1[3] - h13);
            }
            #pragma unroll
            for (int nb = 0; nb < 4; nb++) {
                uint32_t off = SWZ((wn * 32 + kk * 16 + (l & 15)) * 128
                                   + (nb * 16 + (l >> 4) * 8) * 2);
                ldm_x4t(bvh[nb], kst + 16384 + off);
                ldm_x4t(bvl[nb], kst + 24576 + off);
            }
            #pragma unroll
            for (int nd = 0; nd < 8; nd++) {
                mma_bf16(ctx[nd], pah, &bvh[nd >> 1][(nd & 1) * 2]);
                mma_bf16(ctx[nd], pal, &bvh[nd >> 1][(nd & 1) * 2]);
                mma_bf16(ctx[nd], pah, &bvl[nd >> 1][(nd & 1) * 2]);
            }
        }
        __syncthreads();
    }

    // cross-wn reduce via smem (alias KV stage 0), write ctx bf16 hi/lo
    float* red = (float*)(sm + O_KV);   // 64 x 64 fp32 = 16KB
    if (wn == 1) {
        #pragma unroll
        for (int nd = 0; nd < 8; nd++)
            #pragma unroll
            for (int rr = 0; rr < 2; rr++) {
                int row = wm * 16 + rr * 8 + er;
                float2 v;
                v.x = ctx[nd][rr * 2];
                v.y = ctx[nd][rr * 2 + 1];
                *(float2*)&red[row * 64 + nd * 8 + ec] = v;
            }
    }
    __syncthreads();
    if (wn == 0) {
        __nv_bfloat16* Chi = g_c_hi + (size_t)b * SEQ * DM + h * HD;
        __nv_bfloat16* Clo = g_c_lo + (size_t)b * SEQ * DM + h * HD;
        #pragma unroll
        for (int nd = 0; nd < 8; nd++)
            #pragma unroll
            for (int rr = 0; rr < 2; rr++) {
                int row = wm * 16 + rr * 8 + er;
                int col = nd * 8 + ec;
                float2 o = *(float2*)&red[row * 64 + col];
                float vx = ctx[nd][rr * 2] + o.x;
                float vy = ctx[nd][rr * 2 + 1] + o.y;
                float hx = __bfloat162float(__float2bfloat16_rn(vx));
                float hy = __bfloat162float(__float2bfloat16_rn(vy));
                size_t off = (size_t)(m0 + row) * DM + col;
                *(uint32_t*)&Chi[off] = pack_bf2(vx, vy);
                *(uint32_t*)&Clo[off] = pack_bf2(vx - hx, vy - hy);
            }
    }
}

// ---------------------------------------------------------------------------
extern "C" void kernel_launch(void* const* d_in, const int* in_sizes, int n_in,
                              void* d_out, int out_size)
{
    const float* q   = (const float*)d_in[0];
    const float* k   = (const float*)d_in[1];
    const float* v   = (const float*)d_in[2];
    const int*  mask = (const int*)d_in[3];
    const float* Wq  = (const float*)d_in[4];
    const float* Wk  = (const float*)d_in[5];
    const float* Wv  = (const float*)d_in[6];
    const float* Wd  = (const float*)d_in[7];
    const float* bd  = (const float*)d_in[8];
    float* out = (float*)d_out;

    const long long out_elems  = (long long)BQ * SEQ * DM;
    const long long attn_elems = (long long)BQ * NH * SEQ * SEQ;
    float* attn;
    if ((long long)out_size >= out_elems + attn_elems) {
        attn = out + out_elems;
    } else {
        cudaGetSymbolAddress((void**)&attn, g_attn);
    }

    cudaFuncSetAttribute(qkv_gemm,   cudaFuncAttributeMaxDynamicSharedMemorySize, GEMM_SMEM);
    cudaFuncSetAttribute(out_gemm,   cudaFuncAttributeMaxDynamicSharedMemorySize, GEMM_SMEM);
    cudaFuncSetAttribute(attn_pass1, cudaFuncAttributeMaxDynamicSharedMemorySize, P1_SMEM);
    cudaFuncSetAttribute(attn_pass2, cudaFuncAttributeMaxDynamicSharedMemorySize, P2_SMEM);

    uint32_t* mb;
    cudaGetSymbolAddress((void**)&mb, g_mbits);

    prep<<<16384, 256>>>(q, k, v, Wq, Wk, Wv, Wd);

    // z=0..2: projections; z=3: mask packing hidden under GEMM
    qkv_gemm<<<dim3(DM / 128, (BQ * SEQ) / 128, 4), 256, GEMM_SMEM>>>(mask, mb);

    dim3 ga(SEQ / 64, BQ * NH);   // 16 x 64 = 1024 CTAs
    attn_pass1<<<ga, 256, P1_SMEM>>>();
    attn_pass2<<<ga, 256, P2_SMEM>>>(attn);

    out_gemm<<<dim3(DM / 128, (BQ * SEQ) / 128), 256, GEMM_SMEM>>>(bd, out);
}

// round 15
// speedup vs baseline: 1.0914x; 1.0692x over previous
#include <cuda_runtime.h>
#include <cuda_bf16.h>
#include <stdint.h>
#include <math.h>

#define BQ  4
#define SEQ 1024
#define DM  1024
#define NH  16
#define HD  64

// ---------------- scratch (no allocations allowed) ----------------
__device__ float g_attn[BQ * NH * SEQ * SEQ];  // fallback if attn not an output
__device__ float g_rsum[BQ * NH * SEQ];
__device__ uint32_t g_mbits[BQ * SEQ * (SEQ / 32)];

__device__ __nv_bfloat16 g_q_hi[BQ * SEQ * DM],  g_q_lo[BQ * SEQ * DM];
__device__ __nv_bfloat16 g_k_hi[BQ * SEQ * DM],  g_k_lo[BQ * SEQ * DM];
__device__ __nv_bfloat16 g_v_hi[BQ * SEQ * DM],  g_v_lo[BQ * SEQ * DM];
__device__ __nv_bfloat16 g_qp_hi[BQ * SEQ * DM], g_qp_lo[BQ * SEQ * DM];
__device__ __nv_bfloat16 g_kp_hi[BQ * SEQ * DM], g_kp_lo[BQ * SEQ * DM];
__device__ __nv_bfloat16 g_vp_hi[BQ * SEQ * DM], g_vp_lo[BQ * SEQ * DM];
__device__ __nv_bfloat16 g_c_hi[BQ * SEQ * DM],  g_c_lo[BQ * SEQ * DM];
__device__ __nv_bfloat16 g_wq_hi[DM * DM], g_wq_lo[DM * DM];
__device__ __nv_bfloat16 g_wk_hi[DM * DM], g_wk_lo[DM * DM];
__device__ __nv_bfloat16 g_wv_hi[DM * DM], g_wv_lo[DM * DM];
__device__ __nv_bfloat16 g_wd_hi[DM * DM], g_wd_lo[DM * DM];

#define SWZ(o)   ((o) ^ (((o) >> 3) & 0x70))              // 128B rows
#define SWZ32(o) ((o) ^ ((((o) >> 7) & 3) << 4))          // 64B rows

__device__ __forceinline__ uint32_t smem_u32(const void* p) {
    uint32_t a;
    asm("{ .reg .u64 t; cvta.to.shared.u64 t, %1; cvt.u32.u64 %0, t; }" : "=r"(a) : "l"(p));
    return a;
}
__device__ __forceinline__ void ldm_x4(uint32_t* r, uint32_t addr) {
    asm volatile("ldmatrix.sync.aligned.m8n8.x4.shared.b16 {%0,%1,%2,%3}, [%4];"
        : "=r"(r[0]), "=r"(r[1]), "=r"(r[2]), "=r"(r[3]) : "r"(addr));
}
__device__ __forceinline__ void ldm_x4t(uint32_t* r, uint32_t addr) {
    asm volatile("ldmatrix.sync.aligned.m8n8.x4.trans.shared.b16 {%0,%1,%2,%3}, [%4];"
        : "=r"(r[0]), "=r"(r[1]), "=r"(r[2]), "=r"(r[3]) : "r"(addr));
}
__device__ __forceinline__ void mma_bf16(float* d, const uint32_t* a, const uint32_t* b) {
    asm volatile(
        "mma.sync.aligned.m16n8k16.row.col.f32.bf16.bf16.f32 "
        "{%0,%1,%2,%3}, {%4,%5,%6,%7}, {%8,%9}, {%0,%1,%2,%3};"
        : "+f"(d[0]), "+f"(d[1]), "+f"(d[2]), "+f"(d[3])
        : "r"(a[0]), "r"(a[1]), "r"(a[2]), "r"(a[3]), "r"(b[0]), "r"(b[1]));
}
#define CP16(dst, src) asm volatile("cp.async.cg.shared.global [%0], [%1], 16;" :: "r"(dst), "l"(src))
#define CP_COMMIT()    asm volatile("cp.async.commit_group;" ::: "memory")
#define CP_WAIT0()     asm volatile("cp.async.wait_group 0;" ::: "memory")
#define CP_WAIT1()     asm volatile("cp.async.wait_group 1;" ::: "memory")
#define CP_WAIT2()     asm volatile("cp.async.wait_group 2;" ::: "memory")

__device__ __forceinline__ uint32_t pack_bf2(float x, float y) {
    __nv_bfloat162 t(__float2bfloat16_rn(x), __float2bfloat16_rn(y));
    return *(uint32_t*)&t;
}

// ---------------------------------------------------------------------------
// prep: converts ONLY (mask packing runs inside the qkv_gemm launch).
// ---------------------------------------------------------------------------
__device__ __forceinline__ void split_store(
    const float* __restrict__ x, __nv_bfloat16* hi, __nv_bfloat16* lo, int i)
{
    float4 v = ((const float4*)x)[i];
    __nv_bfloat16 h0 = __float2bfloat16_rn(v.x);
    __nv_bfloat16 h1 = __float2bfloat16_rn(v.y);
    __nv_bfloat16 h2 = __float2bfloat16_rn(v.z);
    __nv_bfloat16 h3 = __float2bfloat16_rn(v.w);
    __nv_bfloat16 l0 = __float2bfloat16_rn(v.x - __bfloat162float(h0));
    __nv_bfloat16 l1 = __float2bfloat16_rn(v.y - __bfloat162float(h1));
    __nv_bfloat16 l2 = __float2bfloat16_rn(v.z - __bfloat162float(h2));
    __nv_bfloat16 l3 = __float2bfloat16_rn(v.w - __bfloat162float(h3));
    __nv_bfloat162* hp = (__nv_bfloat162*)(hi + (size_t)i * 4);
    __nv_bfloat162* lp = (__nv_bfloat162*)(lo + (size_t)i * 4);
    hp[0] = __nv_bfloat162(h0, h1); hp[1] = __nv_bfloat162(h2, h3);
    lp[0] = __nv_bfloat162(l0, l1); lp[1] = __nv_bfloat162(l2, l3);
}

__global__ __launch_bounds__(256) void prep(
    const float* __restrict__ q, const float* __restrict__ k,
    const float* __restrict__ v,
    const float* __restrict__ Wq, const float* __restrict__ Wk,
    const float* __restrict__ Wv, const float* __restrict__ Wd)
{
    int bid = blockIdx.x;
    if (bid < 12288) {
        int z = bid >> 12;
        int i = (bid & 4095) * 256 + threadIdx.x;
        if (z == 0)      split_store(q, g_q_hi, g_q_lo, i);
        else if (z == 1) split_store(k, g_k_hi, g_k_lo, i);
        else             split_store(v, g_v_hi, g_v_lo, i);
    } else {
        int r = bid - 12288;
        int z = r >> 10;
        int i = (r & 1023) * 256 + threadIdx.x;
        if (z == 0)      split_store(Wq, g_wq_hi, g_wq_lo, i);
        else if (z == 1) split_store(Wk, g_wk_hi, g_wk_lo, i);
        else if (z == 2) split_store(Wv, g_wv_hi, g_wv_lo, i);
        else             split_store(Wd, g_wd_hi, g_wd_lo, i);
    }
}

// ---------------------------------------------------------------------------
// GEMM body (unchanged): BK=32, 3-stage cp.async, 2 CTAs/SM.
// ---------------------------------------------------------------------------
#define GEMM_SMEM (3 * 32768)

__device__ __forceinline__ void gemm_body(
    const __nv_bfloat16* __restrict__ Ahi, const __nv_bfloat16* __restrict__ Alo,
    const __nv_bfloat16* __restrict__ Whi, const __nv_bfloat16* __restrict__ Wlo,
    const float* __restrict__ bias, float* __restrict__ Cf32,
    __nv_bfloat16* __restrict__ Chi, __nv_bfloat16* __restrict__ Clo,
    char* sm)
{
    const int K = DM, N = DM;

    int tid = threadIdx.x, w = tid >> 5, l = tid & 31;
    int m0 = blockIdx.y * 128, n0 = blockIdx.x * 128;
    int wm = w & 1, wn = w >> 1;

    uint32_t sb = smem_u32(sm);

    int a_row = wm * 64 + (l & 15);
    int a_cb  = (l >> 4) * 16;
    int b_row = wn * 32 + (l & 7) + ((l >> 4) * 8);
    int b_cb  = ((l >> 3) & 1) * 16;

    float acc[4][4][4] = {};
    const int NK = K / 32;

    auto load_stage = [&](int s, int kc) {
        uint32_t base = sb + (uint32_t)s * 32768;
        #pragma unroll
        for (int it = 0; it < 2; it++) {
            int idx = tid + it * 256;
            int row = idx >> 2, c = idx & 3;
            size_t ga = (size_t)(m0 + row) * K + kc * 32 + c * 8;
            size_t gw = (size_t)(n0 + row) * K + kc * 32 + c * 8;
            uint32_t so = SWZ32(row * 64 + c * 16);
            CP16(base +     0 + so, Ahi + ga);
            CP16(base +  8192 + so, Alo + ga);
            CP16(base + 16384 + so, Whi + gw);
            CP16(base + 24576 + so, Wlo + gw);
        }
        CP_COMMIT();
    };

    load_stage(0, 0);
    load_stage(1, 1);

    for (int kc = 0; kc < NK; kc++) {
        __syncthreads();
        if (kc + 2 < NK) { load_stage((kc + 2) % 3, kc + 2); CP_WAIT2(); }
        else if (kc + 1 < NK) { CP_WAIT1(); }
        else { CP_WAIT0(); }
        __syncthreads();

        uint32_t st = sb + (uint32_t)(kc % 3) * 32768;
        #pragma unroll
        for (int kk = 0; kk < 2; kk++) {
            int ks2 = kk * 32;
            uint32_t ah[4][4], al[4][4], bw[2][4];
            #pragma unroll
            for (int mf = 0; mf < 4; mf++) {
                uint32_t off = SWZ32((a_row + mf * 16) * 64 + ks2 + a_cb);
                ldm_x4(ah[mf], st + 0 + off);
                ldm_x4(al[mf], st + 8192 + off);
            }
            #pragma unroll
            for (int bp = 0; bp < 2; bp++) {
                uint32_t off = SWZ32((b_row + bp * 16) * 64 + ks2 + b_cb);
                ldm_x4(bw[bp], st + 16384 + off);
            }
            #pragma unroll
            for (int mf = 0; mf < 4; mf++)
                #pragma unroll
                for (int nf = 0; nf < 4; nf++)
                    mma_bf16(acc[mf][nf], ah[mf], &bw[nf >> 1][(nf & 1) * 2]);
            #pragma unroll
            for (int mf = 0; mf < 4; mf++)
                #pragma unroll
                for (int nf = 0; nf < 4; nf++)
                    mma_bf16(acc[mf][nf], al[mf], &bw[nf >> 1][(nf & 1) * 2]);
            #pragma unroll
            for (int bp = 0; bp < 2; bp++) {
                uint32_t off = SWZ32((b_row + bp * 16) * 64 + ks2 + b_cb);
                ldm_x4(bw[bp], st + 24576 + off);
            }
            #pragma unroll
            for (int mf = 0; mf < 4; mf++)
                #pragma unroll
                for (int nf = 0; nf < 4; nf++)
                    mma_bf16(acc[mf][nf], ah[mf], &bw[nf >> 1][(nf & 1) * 2]);
        }
    }

    int er = l >> 2, ec = (l & 3) * 2;
    #pragma unroll
    for (int mf = 0; mf < 4; mf++) {
        #pragma unroll
        for (int nf = 0; nf < 4; nf++) {
            int gm = m0 + wm * 64 + mf * 16 + er;
            int gn = n0 + wn * 32 + nf * 8 + ec;
            if (Cf32) {
                float b0 = bias ? bias[gn] : 0.0f;
                float b1 = bias ? bias[gn + 1] : 0.0f;
                float2 v0, v1;
                v0.x = acc[mf][nf][0] + b0; v0.y = acc[mf][nf][1] + b1;
                v1.x = acc[mf][nf][2] + b0; v1.y = acc[mf][nf][3] + b1;
                *(float2*)&Cf32[(size_t)gm * N + gn]       = v0;
                *(float2*)&Cf32[(size_t)(gm + 8) * N + gn] = v1;
            } else {
                #pragma unroll
                for (int rr = 0; rr < 2; rr++) {
                    float vx = acc[mf][nf][rr * 2], vy = acc[mf][nf][rr * 2 + 1];
                    float hx = __bfloat162float(__float2bfloat16_rn(vx));
                    float hy = __bfloat162float(__float2bfloat16_rn(vy));
                    size_t o = (size_t)(gm + rr * 8) * N + gn;
                    *(uint32_t*)&Chi[o] = pack_bf2(vx, vy);
                    *(uint32_t*)&Clo[o] = pack_bf2(vx - hx, vy - hy);
                }
            }
        }
    }
}

// z = 0..2: Q/K/V projections. z = 3: mask bit-packing hidden under GEMM.
__global__ __launch_bounds__(256, 2) void qkv_gemm(
    const int* __restrict__ mask, uint32_t* __restrict__ bits)
{
    extern __shared__ char sm[];
    int z = blockIdx.z;
    if (z == 0)
        gemm_body(g_q_hi, g_q_lo, g_wq_hi, g_wq_lo, nullptr, nullptr, g_qp_hi, g_qp_lo, sm);
    else if (z == 1)
        gemm_body(g_k_hi, g_k_lo, g_wk_hi, g_wk_lo, nullptr, nullptr, g_kp_hi, g_kp_lo, sm);
    else if (z == 2)
        gemm_body(g_v_hi, g_v_lo, g_wv_hi, g_wv_lo, nullptr, nullptr, g_vp_hi, g_vp_lo, sm);
    else {
        int flat = (blockIdx.y * gridDim.x + blockIdx.x) * 256 + threadIdx.x;
        #pragma unroll
        for (int t = 0; t < 2; t++) {
            int wdx = flat * 2 + t;
            const int* p = mask + (size_t)wdx * 32;
            uint32_t word = 0;
            #pragma unroll
            for (int j = 0; j < 8; j++) {
                int4 mv = ((const int4*)p)[j];
                word |= (mv.x ? 1u : 0u) << (j * 4 + 0);
                word |= (mv.y ? 1u : 0u) << (j * 4 + 1);
                word |= (mv.z ? 1u : 0u) << (j * 4 + 2);
                word |= (mv.w ? 1u : 0u) << (j * 4 + 3);
            }
            bits[wdx] = word;
        }
    }
}

__global__ __launch_bounds__(256, 2) void out_gemm(const float* __restrict__ bias,
                                                   float* __restrict__ out)
{
    extern __shared__ char sm[];
    gemm_body(g_c_hi, g_c_lo, g_wd_hi, g_wd_lo, bias, out, nullptr, nullptr, sm);
}

// ---------------------------------------------------------------------------
// Attention pass 1 (SUM ONLY, hi-only MMA, no max): 64-row CTAs, 256 threads,
// 64-key double-buffered K-hi tiles. 4 CTAs/SM.
// smem: Qh 8K | Kh stages 2x8K | stats 0.5K = 24.5K
// sum_j exp(s_j) with s = QhKh/32 + mask*(-1e9): lo terms dropped — the
// independent per-key errors (~1.4e-3) average to ~6e-5 in the sum.
// ---------------------------------------------------------------------------
#define P1_SMEM (8192 + 16384 + 512)

__global__ __launch_bounds__(256, 4) void attn_pass1()
{
    extern __shared__ char sm[];
    const uint32_t O_Q = 0, O_K = 8192, O_MS = 24576;

    int tid = threadIdx.x, w = tid >> 5, l = tid & 31;
    int bh = blockIdx.y, b = bh >> 4, h = bh & 15;
    int m0 = blockIdx.x * 64;
    int wm = w & 3, wn = w >> 2;
    uint32_t sb = smem_u32(sm);
    float* sm_s = (float*)(sm + O_MS);     // 2 x 64

    const __nv_bfloat16* Qh = g_qp_hi + (size_t)b * SEQ * DM + h * HD;
    const __nv_bfloat16* Kh = g_kp_hi + (size_t)b * SEQ * DM + h * HD;
    const uint32_t* mrow_bits = g_mbits + ((size_t)b * SEQ) * 32;

    auto load_k = [&](int nt) {
        uint32_t base = sb + O_K + (uint32_t)(nt & 1) * 8192;
        // 8192B / 16B = 512 chunks, 256 threads x 2
        #pragma unroll
        for (int it = 0; it < 2; it++) {
            int idx = tid + it * 256;
            int row = idx >> 3, c = idx & 7;
            uint32_t so = SWZ(row * 128 + c * 16);
            size_t g = (size_t)(nt * 64 + row) * DM + c * 8;
            CP16(base + so, Kh + g);
        }
        CP_COMMIT();
    };

    // Q-hi tile (persistent): 64 rows x 128B
    #pragma unroll
    for (int it = 0; it < 2; it++) {
        int idx = tid + it * 256;
        int row = idx >> 3, c = idx & 7;
        uint32_t so = SWZ(row * 128 + c * 16);
        *(uint4*)(sm + O_Q + so) =
            *(const uint4*)(Qh + (size_t)(m0 + row) * DM + c * 8);
    }
    load_k(0);

    float srun[2] = {};
    const float scale = 0.03125f;
    int er = l >> 2, ec = (l & 3) * 2;

    for (int nt = 0; nt < 16; nt++) {
        if (nt + 1 < 16) { load_k(nt + 1); CP_WAIT1(); }
        else             { CP_WAIT0(); }
        __syncthreads();

        uint32_t kst = sb + O_K + (uint32_t)(nt & 1) * 8192;

        float acc[4][4] = {};
        #pragma unroll
        for (int kk = 0; kk < 4; kk++) {
            int ks2 = kk * 32;
            uint32_t ah[4], bwh[2][4];
            {
                uint32_t off = SWZ((wm * 16 + (l & 15)) * 128 + ks2 + (l >> 4) * 16);
                ldm_x4(ah, sb + O_Q + off);
            }
            #pragma unroll
            for (int bp = 0; bp < 2; bp++) {
                uint32_t off = SWZ((wn * 32 + bp * 16 + (l & 7) + ((l >> 4) * 8)) * 128
                                   + ks2 + ((l >> 3) & 1) * 16);
                ldm_x4(bwh[bp], kst + off);
            }
            #pragma unroll
            for (int nf = 0; nf < 4; nf++)
                mma_bf16(acc[nf], ah, &bwh[nf >> 1][(nf & 1) * 2]);
        }

        #pragma unroll
        for (int rr = 0; rr < 2; rr++) {
            int rl = wm * 16 + rr * 8 + er;
            uint32_t word = mrow_bits[(size_t)(m0 + rl) * 32 + nt * 2 + wn];
            float ts = 0.0f;
            #pragma unroll
            for (int nf = 0; nf < 4; nf++) {
                int sh = nf * 8 + ec;
                float m0f = ((word >> sh) & 1u) ? -1e9f : 0.0f;
                float m1f = ((word >> (sh + 1)) & 1u) ? -1e9f : 0.0f;
                ts += __expf(acc[nf][rr * 2]     * scale + m0f);
                ts += __expf(acc[nf][rr * 2 + 1] * scale + m1f);
            }
            ts += __shfl_xor_sync(0xffffffffu, ts, 1);
            ts += __shfl_xor_sync(0xffffffffu, ts, 2);
            srun[rr] += ts;
        }
        __syncthreads();
    }

    if ((l & 3) == 0) {
        #pragma unroll
        for (int rr = 0; rr < 2; rr++) {
            int rl = wm * 16 + rr * 8 + er;
            sm_s[wn * 64 + rl] = srun[rr];
        }
    }
    __syncthreads();
    if (tid < 64)
        g_rsum[(size_t)bh * SEQ + m0 + tid] = sm_s[tid] + sm_s[64 + tid];
}

// ---------------------------------------------------------------------------
// Attention pass 2 (no max): 64-row CTAs, 64-key double-buffered tiles,
// 2 CTAs/SM. attn = exp(s) * rinv; ctx = P@V (full 3-term precision).
// ---------------------------------------------------------------------------
#define P2_SMEM (16384 + 65536)

__global__ __launch_bounds__(256, 2) void attn_pass2(float* __restrict__ attn)
{
    extern __shared__ char sm[];
    const uint32_t O_Q = 0, O_KV = 16384;

    int tid = threadIdx.x, w = tid >> 5, l = tid & 31;
    int bh = blockIdx.y, b = bh >> 4, h = bh & 15;
    int m0 = blockIdx.x * 64;
    int wm = w & 3, wn = w >> 2;
    uint32_t sb = smem_u32(sm);

    const __nv_bfloat16* Qh = g_qp_hi + (size_t)b * SEQ * DM + h * HD;
    const __nv_bfloat16* Ql = g_qp_lo + (size_t)b * SEQ * DM + h * HD;
    const __nv_bfloat16* Kh = g_kp_hi + (size_t)b * SEQ * DM + h * HD;
    const __nv_bfloat16* Kl = g_kp_lo + (size_t)b * SEQ * DM + h * HD;
    const __nv_bfloat16* Vh = g_vp_hi + (size_t)b * SEQ * DM + h * HD;
    const __nv_bfloat16* Vl = g_vp_lo + (size_t)b * SEQ * DM + h * HD;
    const uint32_t* mrow_bits = g_mbits + ((size_t)b * SEQ) * 32;

    auto load_kv = [&](int nt) {
        uint32_t base = sb + O_KV + (uint32_t)(nt & 1) * 32768;
        #pragma unroll
        for (int it = 0; it < 2; it++) {
            int idx = tid + it * 256;
            int row = idx >> 3, c = idx & 7;
            uint32_t so = SWZ(row * 128 + c * 16);
            size_t g = (size_t)(nt * 64 + row) * DM + c * 8;
            CP16(base + so,         Kh + g);
            CP16(base +  8192 + so, Kl + g);
            CP16(base + 16384 + so, Vh + g);
            CP16(base + 24576 + so, Vl + g);
        }
        CP_COMMIT();
    };

    #pragma unroll
    for (int it = 0; it < 2; it++) {
        int idx = tid + it * 256;
        int row = idx >> 3, c = idx & 7;
        uint32_t so = SWZ(row * 128 + c * 16);
        size_t g = (size_t)(m0 + row) * DM + c * 8;
        *(uint4*)(sm + O_Q + so)        = *(const uint4*)(Qh + g);
        *(uint4*)(sm + O_Q + 8192 + so) = *(const uint4*)(Ql + g);
    }
    load_kv(0);

    int er = l >> 2, ec = (l & 3) * 2;
    const float scale = 0.03125f;

    float rinv[2];
    #pragma unroll
    for (int rr = 0; rr < 2; rr++) {
        int gm = m0 + wm * 16 + rr * 8 + er;
        rinv[rr] = __frcp_rn(g_rsum[(size_t)bh * SEQ + gm]);
    }

    float ctx[8][4] = {};

    for (int nt = 0; nt < 16; nt++) {
        if (nt + 1 < 16) { load_kv(nt + 1); CP_WAIT1(); }
        else             { CP_WAIT0(); }
        __syncthreads();

        uint32_t kst = sb + O_KV + (uint32_t)(nt & 1) * 32768;

        float acc[4][4] = {};
        #pragma unroll
        for (int kk = 0; kk < 4; kk++) {
            int ks2 = kk * 32;
            uint32_t ah[4], al[4], bwh[2][4], bwl[2][4];
            {
                uint32_t off = SWZ((wm * 16 + (l & 15)) * 128 + ks2 + (l >> 4) * 16);
                ldm_x4(ah, sb + O_Q + off);
                ldm_x4(al, sb + O_Q + 8192 + off);
            }
            #pragma unroll
            for (int bp = 0; bp < 2; bp++) {
                uint32_t off = SWZ((wn * 32 + bp * 16 + (l & 7) + ((l >> 4) * 8)) * 128
                                   + ks2 + ((l >> 3) & 1) * 16);
                ldm_x4(bwh[bp], kst + off);
                ldm_x4(bwl[bp], kst + 8192 + off);
            }
            #pragma unroll
            for (int nf = 0; nf < 4; nf++) {
                mma_bf16(acc[nf], ah, &bwh[nf >> 1][(nf & 1) * 2]);
                mma_bf16(acc[nf], al, &bwh[nf >> 1][(nf & 1) * 2]);
                mma_bf16(acc[nf], ah, &bwl[nf >> 1][(nf & 1) * 2]);
            }
        }

        // P = exp(s) * rinv; write attn; keep P in acc
        #pragma unroll
        for (int rr = 0; rr < 2; rr++) {
            int rl = wm * 16 + rr * 8 + er;
            int gm = m0 + rl;
            uint32_t word = mrow_bits[(size_t)gm * 32 + nt * 2 + wn];
            #pragma unroll
            for (int nf = 0; nf < 4; nf++) {
                int sh = nf * 8 + ec;
                float m0f = ((word >> sh) & 1u) ? -1e9f : 0.0f;
                float m1f = ((word >> (sh + 1)) & 1u) ? -1e9f : 0.0f;
                float2 pv;
                pv.x = __expf(acc[nf][rr * 2]     * scale + m0f) * rinv[rr];
                pv.y = __expf(acc[nf][rr * 2 + 1] * scale + m1f) * rinv[rr];
                int gn = nt * 64 + wn * 32 + nf * 8 + ec;
                *(float2*)&attn[((size_t)bh * SEQ + gm) * SEQ + gn] = pv;
                acc[nf][rr * 2]     = pv.x;
                acc[nf][rr * 2 + 1] = pv.y;
            }
        }

        // ctx += P @ V (this warp's 32 keys)
        #pragma unroll
        for (int kk = 0; kk < 2; kk++) {
            uint32_t pah[4], pal[4], bvh[4][4], bvl[4][4];
            {
                float* a0 = acc[kk * 2];
                float* a1 = acc[kk * 2 + 1];
                pah[0] = pack_bf2(a0[0], a0[1]);
                pah[1] = pack_bf2(a0[2], a0[3]);
                pah[2] = pack_bf2(a1[0], a1[1]);
                pah[3] = pack_bf2(a1[2], a1[3]);
                float h00 = __bfloat162float(__float2bfloat16_rn(a0[0]));
                float h01 = __bfloat162float(__float2bfloat16_rn(a0[1]));
                float h02 = __bfloat162float(__float2bfloat16_rn(a0[2]));
                float h03 = __bfloat162float(__float2bfloat16_rn(a0[3]));
                float h10 = __bfloat162float(__float2bfloat16_rn(a1[0]));
                float h11 = __bfloat162float(__float2bfloat16_rn(a1[1]));
                float h12 = __bfloat162float(__float2bfloat16_rn(a1[2]));
                float h13 = __bfloat162float(__float2bfloat16_rn(a1[3]));
                pal[0] = pack_bf2(a0[0] - h00, a0[1] - h01);
                pal[1] = pack_bf2(a0[2] - h02, a0[3] - h03);
                pal[2] = pack_bf2(a1[0] - h10, a1[1] - h11);
                pal[3] = pack_bf2(a1[2] - h12, a1[3] - h13);
            }
            #pragma unroll
            for (int nb = 0; nb < 4; nb++) {
                uint32_t off = SWZ((wn * 32 + kk * 16 + (l & 15)) * 128
                                   + (nb * 16 + (l >> 4) * 8) * 2);
                ldm_x4t(bvh[nb], kst + 16384 + off);
                ldm_x4t(bvl[nb], kst + 24576 + off);
            }
            #pragma unroll
            for (int nd = 0; nd < 8; nd++) {
                mma_bf16(ctx[nd], pah, &bvh[nd >> 1][(nd & 1) * 2]);
                mma_bf16(ctx[nd], pal, &bvh[nd >> 1][(nd & 1) * 2]);
                mma_bf16(ctx[nd], pah, &bvl[nd >> 1][(nd & 1) * 2]);
            }
        }
        __syncthreads();
    }

    // cross-wn reduce via smem (alias KV stage 0), write ctx bf16 hi/lo
    float* red = (float*)(sm + O_KV);   // 64 x 64 fp32 = 16KB
    if (wn == 1) {
        #pragma unroll
        for (int nd = 0; nd < 8; nd++)
            #pragma unroll
            for (int rr = 0; rr < 2; rr++) {
                int row = wm * 16 + rr * 8 + er;
                float2 v;
                v.x = ctx[nd][rr * 2];
                v.y = ctx[nd][rr * 2 + 1];
                *(float2*)&red[row * 64 + nd * 8 + ec] = v;
            }
    }
    __syncthreads();
    if (wn == 0) {
        __nv_bfloat16* Chi = g_c_hi + (size_t)b * SEQ * DM + h * HD;
        __nv_bfloat16* Clo = g_c_lo + (size_t)b * SEQ * DM + h * HD;
        #pragma unroll
        for (int nd = 0; nd < 8; nd++)
            #pragma unroll
            for (int rr = 0; rr < 2; rr++) {
                int row = wm * 16 + rr * 8 + er;
                int col = nd * 8 + ec;
                float2 o = *(float2*)&red[row * 64 + col];
                float vx = ctx[nd][rr * 2] + o.x;
                float vy = ctx[nd][rr * 2 + 1] + o.y;
                float hx = __bfloat162float(__float2bfloat16_rn(vx));
                float hy = __bfloat162float(__float2bfloat16_rn(vy));
                size_t off = (size_t)(m0 + row) * DM + col;
                *(uint32_t*)&Chi[off] = pack_bf2(vx, vy);
                *(uint32_t*)&Clo[off] = pack_bf2(vx - hx, vy - hy);
            }
    }
}

// ---------------------------------------------------------------------------
extern "C" void kernel_launch(void* const* d_in, const int* in_sizes, int n_in,
                              void* d_out, int out_size)
{
    const float* q   = (const float*)d_in[0];
    const float* k   = (const float*)d_in[1];
    const float* v   = (const float*)d_in[2];
    const int*  mask = (const int*)d_in[3];
    const float* Wq  = (const float*)d_in[4];
    const float* Wk  = (const float*)d_in[5];
    const float* Wv  = (const float*)d_in[6];
    const float* Wd  = (const float*)d_in[7];
    const float* bd  = (const float*)d_in[8];
    float* out = (float*)d_out;

    const long long out_elems  = (long long)BQ * SEQ * DM;
    const long long attn_elems = (long long)BQ * NH * SEQ * SEQ;
    float* attn;
    if ((long long)out_size >= out_elems + attn_elems) {
        attn = out + out_elems;
    } else {
        cudaGetSymbolAddress((void**)&attn, g_attn);
    }

    cudaFuncSetAttribute(qkv_gemm,   cudaFuncAttributeMaxDynamicSharedMemorySize, GEMM_SMEM);
    cudaFuncSetAttribute(out_gemm,   cudaFuncAttributeMaxDynamicSharedMemorySize, GEMM_SMEM);
    cudaFuncSetAttribute(attn_pass1, cudaFuncAttributeMaxDynamicSharedMemorySize, P1_SMEM);
    cudaFuncSetAttribute(attn_pass2, cudaFuncAttributeMaxDynamicSharedMemorySize, P2_SMEM);

    uint32_t* mb;
    cudaGetSymbolAddress((void**)&mb, g_mbits);

    prep<<<16384, 256>>>(q, k, v, Wq, Wk, Wv, Wd);

    // z=0..2: projections; z=3: mask packing hidden under GEMM
    qkv_gemm<<<dim3(DM / 128, (BQ * SEQ) / 128, 4), 256, GEMM_SMEM>>>(mask, mb);

    dim3 ga(SEQ / 64, BQ * NH);   // 16 x 64 = 1024 CTAs
    attn_pass1<<<ga, 256, P1_SMEM>>>();
    attn_pass2<<<ga, 256, P2_SMEM>>>(attn);

    out_gemm<<<dim3(DM / 128, (BQ * SEQ) / 128), 256, GEMM_SMEM>>>(bd, out);
}

// round 16
// speedup vs baseline: 1.4300x; 1.3102x over previous
#include <cuda_runtime.h>
#include <cuda_fp16.h>
#include <stdint.h>
#include <math.h>

#define BQ  4
#define SEQ 1024
#define DM  1024
#define NH  16
#define HD  64

// ---------------- scratch (no allocations allowed) ----------------
__device__ float g_attn[BQ * NH * SEQ * SEQ];  // fallback if attn not an output
__device__ float g_rsum[BQ * NH * SEQ];
__device__ uint32_t g_mbits[BQ * SEQ * (SEQ / 32)];

__device__ __half g_q_hi[BQ * SEQ * DM],  g_q_lo[BQ * SEQ * DM];
__device__ __half g_k_hi[BQ * SEQ * DM],  g_k_lo[BQ * SEQ * DM];
__device__ __half g_v_hi[BQ * SEQ * DM],  g_v_lo[BQ * SEQ * DM];
__device__ __half g_qp_hi[BQ * SEQ * DM], g_qp_lo[BQ * SEQ * DM];
__device__ __half g_kp_hi[BQ * SEQ * DM];           // B-side: hi only
__device__ __half g_vp_hi[BQ * SEQ * DM];           // B-side: hi only
__device__ __half g_c_hi[BQ * SEQ * DM],  g_c_lo[BQ * SEQ * DM];
__device__ __half g_wq_hi[DM * DM];
__device__ __half g_wk_hi[DM * DM];
__device__ __half g_wv_hi[DM * DM];
__device__ __half g_wd_hi[DM * DM];

#define SWZ(o)   ((o) ^ (((o) >> 3) & 0x70))              // 128B rows
#define SWZ32(o) ((o) ^ ((((o) >> 7) & 3) << 4))          // 64B rows

__device__ __forceinline__ uint32_t smem_u32(const void* p) {
    uint32_t a;
    asm("{ .reg .u64 t; cvta.to.shared.u64 t, %1; cvt.u32.u64 %0, t; }" : "=r"(a) : "l"(p));
    return a;
}
__device__ __forceinline__ void ldm_x4(uint32_t* r, uint32_t addr) {
    asm volatile("ldmatrix.sync.aligned.m8n8.x4.shared.b16 {%0,%1,%2,%3}, [%4];"
        : "=r"(r[0]), "=r"(r[1]), "=r"(r[2]), "=r"(r[3]) : "r"(addr));
}
__device__ __forceinline__ void ldm_x4t(uint32_t* r, uint32_t addr) {
    asm volatile("ldmatrix.sync.aligned.m8n8.x4.trans.shared.b16 {%0,%1,%2,%3}, [%4];"
        : "=r"(r[0]), "=r"(r[1]), "=r"(r[2]), "=r"(r[3]) : "r"(addr));
}
__device__ __forceinline__ void mma_f16(float* d, const uint32_t* a, const uint32_t* b) {
    asm volatile(
        "mma.sync.aligned.m16n8k16.row.col.f32.f16.f16.f32 "
        "{%0,%1,%2,%3}, {%4,%5,%6,%7}, {%8,%9}, {%0,%1,%2,%3};"
        : "+f"(d[0]), "+f"(d[1]), "+f"(d[2]), "+f"(d[3])
        : "r"(a[0]), "r"(a[1]), "r"(a[2]), "r"(a[3]), "r"(b[0]), "r"(b[1]));
}
#define CP16(dst, src) asm volatile("cp.async.cg.shared.global [%0], [%1], 16;" :: "r"(dst), "l"(src))
#define CP_COMMIT()    asm volatile("cp.async.commit_group;" ::: "memory")
#define CP_WAIT0()     asm volatile("cp.async.wait_group 0;" ::: "memory")
#define CP_WAIT1()     asm volatile("cp.async.wait_group 1;" ::: "memory")
#define CP_WAIT2()     asm volatile("cp.async.wait_group 2;" ::: "memory")

__device__ __forceinline__ uint32_t pack_h2(float x, float y) {
    __half2 t(__float2half_rn(x), __float2half_rn(y));
    return *(uint32_t*)&t;
}

// ---------------------------------------------------------------------------
// prep: converts only. q/k/v -> fp16 hi+lo; W -> fp16 hi only.
// ---------------------------------------------------------------------------
__device__ __forceinline__ void split_store_hl(
    const float* __restrict__ x, __half* hi, __half* lo, int i)
{
    float4 v = ((const float4*)x)[i];
    __half h0 = __float2half_rn(v.x);
    __half h1 = __float2half_rn(v.y);
    __half h2 = __float2half_rn(v.z);
    __half h3 = __float2half_rn(v.w);
    __half l0 = __float2half_rn(v.x - __half2float(h0));
    __half l1 = __float2half_rn(v.y - __half2float(h1));
    __half l2 = __float2half_rn(v.z - __half2float(h2));
    __half l3 = __float2half_rn(v.w - __half2float(h3));
    __half2* hp = (__half2*)(hi + (size_t)i * 4);
    __half2* lp = (__half2*)(lo + (size_t)i * 4);
    hp[0] = __half2(h0, h1); hp[1] = __half2(h2, h3);
    lp[0] = __half2(l0, l1); lp[1] = __half2(l2, l3);
}
__device__ __forceinline__ void split_store_h(
    const float* __restrict__ x, __half* hi, int i)
{
    float4 v = ((const float4*)x)[i];
    __half2* hp = (__half2*)(hi + (size_t)i * 4);
    hp[0] = __half2(__float2half_rn(v.x), __float2half_rn(v.y));
    hp[1] = __half2(__float2half_rn(v.z), __float2half_rn(v.w));
}

__global__ __launch_bounds__(256) void prep(
    const float* __restrict__ q, const float* __restrict__ k,
    const float* __restrict__ v,
    const float* __restrict__ Wq, const float* __restrict__ Wk,
    const float* __restrict__ Wv, const float* __restrict__ Wd)
{
    int bid = blockIdx.x;
    if (bid < 12288) {
        int z = bid >> 12;
        int i = (bid & 4095) * 256 + threadIdx.x;
        if (z == 0)      split_store_hl(q, g_q_hi, g_q_lo, i);
        else if (z == 1) split_store_hl(k, g_k_hi, g_k_lo, i);
        else             split_store_hl(v, g_v_hi, g_v_lo, i);
    } else {
        int r = bid - 12288;
        int z = r >> 10;
        int i = (r & 1023) * 256 + threadIdx.x;
        if (z == 0)      split_store_h(Wq, g_wq_hi, i);
        else if (z == 1) split_store_h(Wk, g_wk_hi, i);
        else if (z == 2) split_store_h(Wv, g_wv_hi, i);
        else             split_store_h(Wd, g_wd_hi, i);
    }
}

// ---------------------------------------------------------------------------
// GEMM body: 2-term fp16 split (AhWh + AlWh). BK=32, 3-stage cp.async.
// Stage = Ah 8K | Al 8K | Wh 8K = 24K; 3 stages = 72K; 2 CTAs/SM.
// ---------------------------------------------------------------------------
#define GEMM_SMEM (3 * 24576)

__device__ __forceinline__ void gemm_body(
    const __half* __restrict__ Ahi, const __half* __restrict__ Alo,
    const __half* __restrict__ Whi,
    const float* __restrict__ bias, float* __restrict__ Cf32,
    __half* __restrict__ Chi, __half* __restrict__ Clo,
    char* sm)
{
    const int K = DM, N = DM;

    int tid = threadIdx.x, w = tid >> 5, l = tid & 31;
    int m0 = blockIdx.y * 128, n0 = blockIdx.x * 128;
    int wm = w & 1, wn = w >> 1;

    uint32_t sb = smem_u32(sm);

    int a_row = wm * 64 + (l & 15);
    int a_cb  = (l >> 4) * 16;
    int b_row = wn * 32 + (l & 7) + ((l >> 4) * 8);
    int b_cb  = ((l >> 3) & 1) * 16;

    float acc[4][4][4] = {};
    const int NK = K / 32;

    auto load_stage = [&](int s, int kc) {
        uint32_t base = sb + (uint32_t)s * 24576;
        #pragma unroll
        for (int it = 0; it < 2; it++) {
            int idx = tid + it * 256;
            int row = idx >> 2, c = idx & 3;
            size_t ga = (size_t)(m0 + row) * K + kc * 32 + c * 8;
            size_t gw = (size_t)(n0 + row) * K + kc * 32 + c * 8;
            uint32_t so = SWZ32(row * 64 + c * 16);
            CP16(base +     0 + so, Ahi + ga);
            CP16(base +  8192 + so, Alo + ga);
            CP16(base + 16384 + so, Whi + gw);
        }
        CP_COMMIT();
    };

    load_stage(0, 0);
    load_stage(1, 1);

    for (int kc = 0; kc < NK; kc++) {
        __syncthreads();
        if (kc + 2 < NK) { load_stage((kc + 2) % 3, kc + 2); CP_WAIT2(); }
        else if (kc + 1 < NK) { CP_WAIT1(); }
        else { CP_WAIT0(); }
        __syncthreads();

        uint32_t st = sb + (uint32_t)(kc % 3) * 24576;
        #pragma unroll
        for (int kk = 0; kk < 2; kk++) {
            int ks2 = kk * 32;
            uint32_t ah[4][4], al[4][4], bw[2][4];
            #pragma unroll
            for (int mf = 0; mf < 4; mf++) {
                uint32_t off = SWZ32((a_row + mf * 16) * 64 + ks2 + a_cb);
                ldm_x4(ah[mf], st + 0 + off);
                ldm_x4(al[mf], st + 8192 + off);
            }
            #pragma unroll
            for (int bp = 0; bp < 2; bp++) {
                uint32_t off = SWZ32((b_row + bp * 16) * 64 + ks2 + b_cb);
                ldm_x4(bw[bp], st + 16384 + off);
            }
            #pragma unroll
            for (int mf = 0; mf < 4; mf++)
                #pragma unroll
                for (int nf = 0; nf < 4; nf++)
                    mma_f16(acc[mf][nf], ah[mf], &bw[nf >> 1][(nf & 1) * 2]);
            #pragma unroll
            for (int mf = 0; mf < 4; mf++)
                #pragma unroll
                for (int nf = 0; nf < 4; nf++)
                    mma_f16(acc[mf][nf], al[mf], &bw[nf >> 1][(nf & 1) * 2]);
        }
    }

    int er = l >> 2, ec = (l & 3) * 2;
    #pragma unroll
    for (int mf = 0; mf < 4; mf++) {
        #pragma unroll
        for (int nf = 0; nf < 4; nf++) {
            int gm = m0 + wm * 64 + mf * 16 + er;
            int gn = n0 + wn * 32 + nf * 8 + ec;
            if (Cf32) {
                float b0 = bias ? bias[gn] : 0.0f;
                float b1 = bias ? bias[gn + 1] : 0.0f;
                float2 v0, v1;
                v0.x = acc[mf][nf][0] + b0; v0.y = acc[mf][nf][1] + b1;
                v1.x = acc[mf][nf][2] + b0; v1.y = acc[mf][nf][3] + b1;
                *(float2*)&Cf32[(size_t)gm * N + gn]       = v0;
                *(float2*)&Cf32[(size_t)(gm + 8) * N + gn] = v1;
            } else {
                #pragma unroll
                for (int rr = 0; rr < 2; rr++) {
                    float vx = acc[mf][nf][rr * 2], vy = acc[mf][nf][rr * 2 + 1];
                    size_t o = (size_t)(gm + rr * 8) * N + gn;
                    *(uint32_t*)&Chi[o] = pack_h2(vx, vy);
                    if (Clo) {
                        float hx = __half2float(__float2half_rn(vx));
                        float hy = __half2float(__float2half_rn(vy));
                        *(uint32_t*)&Clo[o] = pack_h2(vx - hx, vy - hy);
                    }
                }
            }
        }
    }
}

// z = 0..2: Q/K/V projections (Q stores hi+lo; K/V hi only).
// z = 3: mask bit-packing hidden under the GEMM.
__global__ __launch_bounds__(256, 2) void qkv_gemm(
    const int* __restrict__ mask, uint32_t* __restrict__ bits)
{
    extern __shared__ char sm[];
    int z = blockIdx.z;
    if (z == 0)
        gemm_body(g_q_hi, g_q_lo, g_wq_hi, nullptr, nullptr, g_qp_hi, g_qp_lo, sm);
    else if (z == 1)
        gemm_body(g_k_hi, g_k_lo, g_wk_hi, nullptr, nullptr, g_kp_hi, nullptr, sm);
    else if (z == 2)
        gemm_body(g_v_hi, g_v_lo, g_wv_hi, nullptr, nullptr, g_vp_hi, nullptr, sm);
    else {
        int flat = (blockIdx.y * gridDim.x + blockIdx.x) * 256 + threadIdx.x;
        #pragma unroll
        for (int t = 0; t < 2; t++) {
            int wdx = flat * 2 + t;
            const int* p = mask + (size_t)wdx * 32;
            uint32_t word = 0;
            #pragma unroll
            for (int j = 0; j < 8; j++) {
                int4 mv = ((const int4*)p)[j];
                word |= (mv.x ? 1u : 0u) << (j * 4 + 0);
                word |= (mv.y ? 1u : 0u) << (j * 4 + 1);
                word |= (mv.z ? 1u : 0u) << (j * 4 + 2);
                word |= (mv.w ? 1u : 0u) << (j * 4 + 3);
            }
            bits[wdx] = word;
        }
    }
}

__global__ __launch_bounds__(256, 2) void out_gemm(const float* __restrict__ bias,
                                                   float* __restrict__ out)
{
    extern __shared__ char sm[];
    gemm_body(g_c_hi, g_c_lo, g_wd_hi, bias, out, nullptr, nullptr, sm);
}

// ---------------------------------------------------------------------------
// Attention pass 1 (SUM ONLY, Qh*Kh): 64-row CTAs, 64-key double-buffered
// K-hi tiles, 4 CTAs/SM. smem: Qh 8K | Kh 2x8K | stats 0.5K
// ---------------------------------------------------------------------------
#define P1_SMEM (8192 + 16384 + 512)

__global__ __launch_bounds__(256, 4) void attn_pass1()
{
    extern __shared__ char sm[];
    const uint32_t O_Q = 0, O_K = 8192, O_MS = 24576;

    int tid = threadIdx.x, w = tid >> 5, l = tid & 31;
    int bh = blockIdx.y, b = bh >> 4, h = bh & 15;
    int m0 = blockIdx.x * 64;
    int wm = w & 3, wn = w >> 2;
    uint32_t sb = smem_u32(sm);
    float* sm_s = (float*)(sm + O_MS);

    const __half* Qh = g_qp_hi + (size_t)b * SEQ * DM + h * HD;
    const __half* Kh = g_kp_hi + (size_t)b * SEQ * DM + h * HD;
    const uint32_t* mrow_bits = g_mbits + ((size_t)b * SEQ) * 32;

    auto load_k = [&](int nt) {
        uint32_t base = sb + O_K + (uint32_t)(nt & 1) * 8192;
        #pragma unroll
        for (int it = 0; it < 2; it++) {
            int idx = tid + it * 256;
            int row = idx >> 3, c = idx & 7;
            uint32_t so = SWZ(row * 128 + c * 16);
            CP16(base + so, Kh + (size_t)(nt * 64 + row) * DM + c * 8);
        }
        CP_COMMIT();
    };

    #pragma unroll
    for (int it = 0; it < 2; it++) {
        int idx = tid + it * 256;
        int row = idx >> 3, c = idx & 7;
        uint32_t so = SWZ(row * 128 + c * 16);
        *(uint4*)(sm + O_Q + so) =
            *(const uint4*)(Qh + (size_t)(m0 + row) * DM + c * 8);
    }
    load_k(0);

    float srun[2] = {};
    const float scale = 0.03125f;
    int er = l >> 2, ec = (l & 3) * 2;

    for (int nt = 0; nt < 16; nt++) {
        if (nt + 1 < 16) { load_k(nt + 1); CP_WAIT1(); }
        else             { CP_WAIT0(); }
        __syncthreads();

        uint32_t kst = sb + O_K + (uint32_t)(nt & 1) * 8192;

        float acc[4][4] = {};
        #pragma unroll
        for (int kk = 0; kk < 4; kk++) {
            int ks2 = kk * 32;
            uint32_t ah[4], bwh[2][4];
            {
                uint32_t off = SWZ((wm * 16 + (l & 15)) * 128 + ks2 + (l >> 4) * 16);
                ldm_x4(ah, sb + O_Q + off);
            }
            #pragma unroll
            for (int bp = 0; bp < 2; bp++) {
                uint32_t off = SWZ((wn * 32 + bp * 16 + (l & 7) + ((l >> 4) * 8)) * 128
                                   + ks2 + ((l >> 3) & 1) * 16);
                ldm_x4(bwh[bp], kst + off);
            }
            #pragma unroll
            for (int nf = 0; nf < 4; nf++)
                mma_f16(acc[nf], ah, &bwh[nf >> 1][(nf & 1) * 2]);
        }

        #pragma unroll
        for (int rr = 0; rr < 2; rr++) {
            int rl = wm * 16 + rr * 8 + er;
            uint32_t word = mrow_bits[(size_t)(m0 + rl) * 32 + nt * 2 + wn];
            float ts = 0.0f;
            #pragma unroll
            for (int nf = 0; nf < 4; nf++) {
                int sh = nf * 8 + ec;
                float m0f = ((word >> sh) & 1u) ? -1e9f : 0.0f;
                float m1f = ((word >> (sh + 1)) & 1u) ? -1e9f : 0.0f;
                ts += __expf(acc[nf][rr * 2]     * scale + m0f);
                ts += __expf(acc[nf][rr * 2 + 1] * scale + m1f);
            }
            ts += __shfl_xor_sync(0xffffffffu, ts, 1);
            ts += __shfl_xor_sync(0xffffffffu, ts, 2);
            srun[rr] += ts;
        }
        __syncthreads();
    }

    if ((l & 3) == 0) {
        #pragma unroll
        for (int rr = 0; rr < 2; rr++) {
            int rl = wm * 16 + rr * 8 + er;
            sm_s[wn * 64 + rl] = srun[rr];
        }
    }
    __syncthreads();
    if (tid < 64)
        g_rsum[(size_t)bh * SEQ + m0 + tid] = sm_s[tid] + sm_s[64 + tid];
}

// ---------------------------------------------------------------------------
// Attention pass 2: 2-term fp16. QK = (Qh+Ql)*Kh; PV = (Ph+Pl)*Vh.
// 64-row CTAs, 64-key double-buffered tiles (Kh 8K + Vh 8K per stage).
// smem: Q 16K | KV 2x16K = 48K; 2 CTAs/SM (reg-capped).
// ---------------------------------------------------------------------------
#define P2_SMEM (16384 + 32768)

__global__ __launch_bounds__(256, 2) void attn_pass2(float* __restrict__ attn)
{
    extern __shared__ char sm[];
    const uint32_t O_Q = 0, O_KV = 16384;

    int tid = threadIdx.x, w = tid >> 5, l = tid & 31;
    int bh = blockIdx.y, b = bh >> 4, h = bh & 15;
    int m0 = blockIdx.x * 64;
    int wm = w & 3, wn = w >> 2;
    uint32_t sb = smem_u32(sm);

    const __half* Qh = g_qp_hi + (size_t)b * SEQ * DM + h * HD;
    const __half* Ql = g_qp_lo + (size_t)b * SEQ * DM + h * HD;
    const __half* Kh = g_kp_hi + (size_t)b * SEQ * DM + h * HD;
    const __half* Vh = g_vp_hi + (size_t)b * SEQ * DM + h * HD;
    const uint32_t* mrow_bits = g_mbits + ((size_t)b * SEQ) * 32;

    auto load_kv = [&](int nt) {
        uint32_t base = sb + O_KV + (uint32_t)(nt & 1) * 16384;
        #pragma unroll
        for (int it = 0; it < 2; it++) {
            int idx = tid + it * 256;
            int row = idx >> 3, c = idx & 7;
            uint32_t so = SWZ(row * 128 + c * 16);
            size_t g = (size_t)(nt * 64 + row) * DM + c * 8;
            CP16(base + so,        Kh + g);
            CP16(base + 8192 + so, Vh + g);
        }
        CP_COMMIT();
    };

    #pragma unroll
    for (int it = 0; it < 2; it++) {
        int idx = tid + it * 256;
        int row = idx >> 3, c = idx & 7;
        uint32_t so = SWZ(row * 128 + c * 16);
        size_t g = (size_t)(m0 + row) * DM + c * 8;
        *(uint4*)(sm + O_Q + so)        = *(const uint4*)(Qh + g);
        *(uint4*)(sm + O_Q + 8192 + so) = *(const uint4*)(Ql + g);
    }
    load_kv(0);

    int er = l >> 2, ec = (l & 3) * 2;
    const float scale = 0.03125f;

    float rinv[2];
    #pragma unroll
    for (int rr = 0; rr < 2; rr++) {
        int gm = m0 + wm * 16 + rr * 8 + er;
        rinv[rr] = __frcp_rn(g_rsum[(size_t)bh * SEQ + gm]);
    }

    float ctx[8][4] = {};

    for (int nt = 0; nt < 16; nt++) {
        if (nt + 1 < 16) { load_kv(nt + 1); CP_WAIT1(); }
        else             { CP_WAIT0(); }
        __syncthreads();

        uint32_t kst = sb + O_KV + (uint32_t)(nt & 1) * 16384;

        float acc[4][4] = {};
        #pragma unroll
        for (int kk = 0; kk < 4; kk++) {
            int ks2 = kk * 32;
            uint32_t ah[4], al[4], bwh[2][4];
            {
                uint32_t off = SWZ((wm * 16 + (l & 15)) * 128 + ks2 + (l >> 4) * 16);
                ldm_x4(ah, sb + O_Q + off);
                ldm_x4(al, sb + O_Q + 8192 + off);
            }
            #pragma unroll
            for (int bp = 0; bp < 2; bp++) {
                uint32_t off = SWZ((wn * 32 + bp * 16 + (l & 7) + ((l >> 4) * 8)) * 128
                                   + ks2 + ((l >> 3) & 1) * 16);
                ldm_x4(bwh[bp], kst + off);
            }
            #pragma unroll
            for (int nf = 0; nf < 4; nf++) {
                mma_f16(acc[nf], ah, &bwh[nf >> 1][(nf & 1) * 2]);
                mma_f16(acc[nf], al, &bwh[nf >> 1][(nf & 1) * 2]);
            }
        }

        // P = exp(s) * rinv; write attn; keep P in acc
        #pragma unroll
        for (int rr = 0; rr < 2; rr++) {
            int rl = wm * 16 + rr * 8 + er;
            int gm = m0 + rl;
            uint32_t word = mrow_bits[(size_t)gm * 32 + nt * 2 + wn];
            #pragma unroll
            for (int nf = 0; nf < 4; nf++) {
                int sh = nf * 8 + ec;
                float m0f = ((word >> sh) & 1u) ? -1e9f : 0.0f;
                float m1f = ((word >> (sh + 1)) & 1u) ? -1e9f : 0.0f;
                float2 pv;
                pv.x = __expf(acc[nf][rr * 2]     * scale + m0f) * rinv[rr];
                pv.y = __expf(acc[nf][rr * 2 + 1] * scale + m1f) * rinv[rr];
                int gn = nt * 64 + wn * 32 + nf * 8 + ec;
                *(float2*)&attn[((size_t)bh * SEQ + gm) * SEQ + gn] = pv;
                acc[nf][rr * 2]     = pv.x;
                acc[nf][rr * 2 + 1] = pv.y;
            }
        }

        // ctx += P @ Vh (2-term P split)
        #pragma unroll
        for (int kk = 0; kk < 2; kk++) {
            uint32_t pah[4], pal[4], bvh[4][4];
            {
                float* a0 = acc[kk * 2];
                float* a1 = acc[kk * 2 + 1];
                pah[0] = pack_h2(a0[0], a0[1]);
                pah[1] = pack_h2(a0[2], a0[3]);
                pah[2] = pack_h2(a1[0], a1[1]);
                pah[3] = pack_h2(a1[2], a1[3]);
                float h00 = __half2float(__float2half_rn(a0[0]));
                float h01 = __half2float(__float2half_rn(a0[1]));
                float h02 = __half2float(__float2half_rn(a0[2]));
                float h03 = __half2float(__float2half_rn(a0[3]));
                float h10 = __half2float(__float2half_rn(a1[0]));
                float h11 = __half2float(__float2half_rn(a1[1]));
                float h12 = __half2float(__float2half_rn(a1[2]));
                float h13 = __half2float(__float2half_rn(a1[3]));
                pal[0] = pack_h2(a0[0] - h00, a0[1] - h01);
                pal[1] = pack_h2(a0[2] - h02, a0[3] - h03);
                pal[2] = pack_h2(a1[0] - h10, a1[1] - h11);
                pal[3] = pack_h2(a1[2] - h12, a1[3] - h13);
            }
            #pragma unroll
            for (int nb = 0; nb < 4; nb++) {
                uint32_t off = SWZ((wn * 32 + kk * 16 + (l & 15)) * 128
                                   + (nb * 16 + (l >> 4) * 8) * 2);
                ldm_x4t(bvh[nb], kst + 8192 + off);
            }
            #pragma unroll
            for (int nd = 0; nd < 8; nd++) {
                mma_f16(ctx[nd], pah, &bvh[nd >> 1][(nd & 1) * 2]);
                mma_f16(ctx[nd], pal, &bvh[nd >> 1][(nd & 1) * 2]);
            }
        }
        __syncthreads();
    }

    // cross-wn reduce via smem (alias KV), write ctx fp16 hi/lo
    float* red = (float*)(sm + O_KV);   // 64 x 64 fp32 = 16KB
    if (wn == 1) {
        #pragma unroll
        for (int nd = 0; nd < 8; nd++)
            #pragma unroll
            for (int rr = 0; rr < 2; rr++) {
                int row = wm * 16 + rr * 8 + er;
                float2 v;
                v.x = ctx[nd][rr * 2];
                v.y = ctx[nd][rr * 2 + 1];
                *(float2*)&red[row * 64 + nd * 8 + ec] = v;
            }
    }
    __syncthreads();
    if (wn == 0) {
        __half* Chi = g_c_hi + (size_t)b * SEQ * DM + h * HD;
        __half* Clo = g_c_lo + (size_t)b * SEQ * DM + h * HD;
        #pragma unroll
        for (int nd = 0; nd < 8; nd++)
            #pragma unroll
            for (int rr = 0; rr < 2; rr++) {
                int row = wm * 16 + rr * 8 + er;
                int col = nd * 8 + ec;
                float2 o = *(float2*)&red[row * 64 + col];
                float vx = ctx[nd][rr * 2] + o.x;
                float vy = ctx[nd][rr * 2 + 1] + o.y;
                float hx = __half2float(__float2half_rn(vx));
                float hy = __half2float(__float2half_rn(vy));
                size_t off = (size_t)(m0 + row) * DM + col;
                *(uint32_t*)&Chi[off] = pack_h2(vx, vy);
                *(uint32_t*)&Clo[off] = pack_h2(vx - hx, vy - hy);
            }
    }
}

// ---------------------------------------------------------------------------
extern "C" void kernel_launch(void* const* d_in, const int* in_sizes, int n_in,
                              void* d_out, int out_size)
{
    const float* q   = (const float*)d_in[0];
    const float* k   = (const float*)d_in[1];
    const float* v   = (const float*)d_in[2];
    const int*  mask = (const int*)d_in[3];
    const float* Wq  = (const float*)d_in[4];
    const float* Wk  = (const float*)d_in[5];
    const float* Wv  = (const float*)d_in[6];
    const float* Wd  = (const float*)d_in[7];
    const float* bd  = (const float*)d_in[8];
    float* out = (float*)d_out;

    const long long out_elems  = (long long)BQ * SEQ * DM;
    const long long attn_elems = (long long)BQ * NH * SEQ * SEQ;
    float* attn;
    if ((long long)out_size >= out_elems + attn_elems) {
        attn = out + out_elems;
    } else {
        cudaGetSymbolAddress((void**)&attn, g_attn);
    }

    cudaFuncSetAttribute(qkv_gemm,   cudaFuncAttributeMaxDynamicSharedMemorySize, GEMM_SMEM);
    cudaFuncSetAttribute(out_gemm,   cudaFuncAttributeMaxDynamicSharedMemorySize, GEMM_SMEM);
    cudaFuncSetAttribute(attn_pass1, cudaFuncAttributeMaxDynamicSharedMemorySize, P1_SMEM);
    cudaFuncSetAttribute(attn_pass2, cudaFuncAttributeMaxDynamicSharedMemorySize, P2_SMEM);

    uint32_t* mb;
    cudaGetSymbolAddress((void**)&mb, g_mbits);

    prep<<<16384, 256>>>(q, k, v, Wq, Wk, Wv, Wd);

    // z=0..2: projections; z=3: mask packing hidden under GEMM
    qkv_gemm<<<dim3(DM / 128, (BQ * SEQ) / 128, 4), 256, GEMM_SMEM>>>(mask, mb);

    dim3 ga(SEQ / 64, BQ * NH);   // 16 x 64 = 1024 CTAs
    attn_pass1<<<ga, 256, P1_SMEM>>>();
    attn_pass2<<<ga, 256, P2_SMEM>>>(attn);

    out_gemm<<<dim3(DM / 128, (BQ * SEQ) / 128), 256, GEMM_SMEM>>>(bd, out);
}

// round 17
// speedup vs baseline: 1.8220x; 1.2741x over previous
#include <cuda_runtime.h>
#include <cuda_fp16.h>
#include <stdint.h>
#include <math.h>

#define BQ  4
#define SEQ 1024
#define DM  1024
#define NH  16
#define HD  64

// ---------------- scratch (no allocations allowed) ----------------
__device__ float g_attn[BQ * NH * SEQ * SEQ];  // fallback if attn not an output
__device__ float g_rsum[BQ * NH * SEQ];
__device__ uint32_t g_mbits[BQ * SEQ * (SEQ / 32)];

__device__ __half g_q_hi[BQ * SEQ * DM];
__device__ __half g_k_hi[BQ * SEQ * DM];
__device__ __half g_v_hi[BQ * SEQ * DM];
__device__ __half g_qp_hi[BQ * SEQ * DM];
__device__ __half g_kp_hi[BQ * SEQ * DM];
__device__ __half g_vp_hi[BQ * SEQ * DM];
__device__ __half g_c_hi[BQ * SEQ * DM], g_c_lo[BQ * SEQ * DM];
__device__ __half g_wq_hi[DM * DM];
__device__ __half g_wk_hi[DM * DM];
__device__ __half g_wv_hi[DM * DM];
__device__ __half g_wd_hi[DM * DM];

#define SWZ(o)   ((o) ^ (((o) >> 3) & 0x70))              // 128B rows
#define SWZ32(o) ((o) ^ ((((o) >> 7) & 3) << 4))          // 64B rows

__device__ __forceinline__ uint32_t smem_u32(const void* p) {
    uint32_t a;
    asm("{ .reg .u64 t; cvta.to.shared.u64 t, %1; cvt.u32.u64 %0, t; }" : "=r"(a) : "l"(p));
    return a;
}
__device__ __forceinline__ void ldm_x4(uint32_t* r, uint32_t addr) {
    asm volatile("ldmatrix.sync.aligned.m8n8.x4.shared.b16 {%0,%1,%2,%3}, [%4];"
        : "=r"(r[0]), "=r"(r[1]), "=r"(r[2]), "=r"(r[3]) : "r"(addr));
}
__device__ __forceinline__ void ldm_x4t(uint32_t* r, uint32_t addr) {
    asm volatile("ldmatrix.sync.aligned.m8n8.x4.trans.shared.b16 {%0,%1,%2,%3}, [%4];"
        : "=r"(r[0]), "=r"(r[1]), "=r"(r[2]), "=r"(r[3]) : "r"(addr));
}
__device__ __forceinline__ void mma_f16(float* d, const uint32_t* a, const uint32_t* b) {
    asm volatile(
        "mma.sync.aligned.m16n8k16.row.col.f32.f16.f16.f32 "
        "{%0,%1,%2,%3}, {%4,%5,%6,%7}, {%8,%9}, {%0,%1,%2,%3};"
        : "+f"(d[0]), "+f"(d[1]), "+f"(d[2]), "+f"(d[3])
        : "r"(a[0]), "r"(a[1]), "r"(a[2]), "r"(a[3]), "r"(b[0]), "r"(b[1]));
}
#define CP16(dst, src) asm volatile("cp.async.cg.shared.global [%0], [%1], 16;" :: "r"(dst), "l"(src))
#define CP_COMMIT()    asm volatile("cp.async.commit_group;" ::: "memory")
#define CP_WAIT0()     asm volatile("cp.async.wait_group 0;" ::: "memory")
#define CP_WAIT1()     asm volatile("cp.async.wait_group 1;" ::: "memory")
#define CP_WAIT2()     asm volatile("cp.async.wait_group 2;" ::: "memory")

__device__ __forceinline__ uint32_t pack_h2(float x, float y) {
    __half2 t(__float2half_rn(x), __float2half_rn(y));
    return *(uint32_t*)&t;
}

// ---------------------------------------------------------------------------
// prep: fp32 -> fp16 hi-only converts for q,k,v and all weights.
// ---------------------------------------------------------------------------
__device__ __forceinline__ void split_store_h(
    const float* __restrict__ x, __half* hi, int i)
{
    float4 v = ((const float4*)x)[i];
    __half2* hp = (__half2*)(hi + (size_t)i * 4);
    hp[0] = __half2(__float2half_rn(v.x), __float2half_rn(v.y));
    hp[1] = __half2(__float2half_rn(v.z), __float2half_rn(v.w));
}

__global__ __launch_bounds__(256) void prep(
    const float* __restrict__ q, const float* __restrict__ k,
    const float* __restrict__ v,
    const float* __restrict__ Wq, const float* __restrict__ Wk,
    const float* __restrict__ Wv, const float* __restrict__ Wd)
{
    int bid = blockIdx.x;
    if (bid < 12288) {
        int z = bid >> 12;
        int i = (bid & 4095) * 256 + threadIdx.x;
        if (z == 0)      split_store_h(q, g_q_hi, i);
        else if (z == 1) split_store_h(k, g_k_hi, i);
        else             split_store_h(v, g_v_hi, i);
    } else {
        int r = bid - 12288;
        int z = r >> 10;
        int i = (r & 1023) * 256 + threadIdx.x;
        if (z == 0)      split_store_h(Wq, g_wq_hi, i);
        else if (z == 1) split_store_h(Wk, g_wk_hi, i);
        else if (z == 2) split_store_h(Wv, g_wv_hi, i);
        else             split_store_h(Wd, g_wd_hi, i);
    }
}

// ---------------------------------------------------------------------------
// GEMM body: TWO=false -> Ah*Wh (1 term); TWO=true -> (Ah+Al)*Wh (2 terms).
// BK=32, 3-stage cp.async, CTA 128x128, 8 warps (64x32), 2 CTAs/SM.
// ---------------------------------------------------------------------------
#define GEMM_SMEM1 (3 * 16384)
#define GEMM_SMEM2 (3 * 24576)

template<bool TWO>
__device__ __forceinline__ void gemm_body(
    const __half* __restrict__ Ahi, const __half* __restrict__ Alo,
    const __half* __restrict__ Whi,
    const float* __restrict__ bias, float* __restrict__ Cf32,
    __half* __restrict__ Chi, __half* __restrict__ Clo,
    char* sm)
{
    const int K = DM, N = DM;
    const uint32_t STG  = TWO ? 24576 : 16384;
    const uint32_t O_WH = TWO ? 16384 : 8192;

    int tid = threadIdx.x, w = tid >> 5, l = tid & 31;
    int m0 = blockIdx.y * 128, n0 = blockIdx.x * 128;
    int wm = w & 1, wn = w >> 1;

    uint32_t sb = smem_u32(sm);

    int a_row = wm * 64 + (l & 15);
    int a_cb  = (l >> 4) * 16;
    int b_row = wn * 32 + (l & 7) + ((l >> 4) * 8);
    int b_cb  = ((l >> 3) & 1) * 16;

    float acc[4][4][4] = {};
    const int NK = K / 32;

    auto load_stage = [&](int s, int kc) {
        uint32_t base = sb + (uint32_t)s * STG;
        #pragma unroll
        for (int it = 0; it < 2; it++) {
            int idx = tid + it * 256;
            int row = idx >> 2, c = idx & 3;
            size_t ga = (size_t)(m0 + row) * K + kc * 32 + c * 8;
            size_t gw = (size_t)(n0 + row) * K + kc * 32 + c * 8;
            uint32_t so = SWZ32(row * 64 + c * 16);
            CP16(base + so, Ahi + ga);
            if (TWO) CP16(base + 8192 + so, Alo + ga);
            CP16(base + O_WH + so, Whi + gw);
        }
        CP_COMMIT();
    };

    load_stage(0, 0);
    load_stage(1, 1);

    for (int kc = 0; kc < NK; kc++) {
        __syncthreads();
        if (kc + 2 < NK) { load_stage((kc + 2) % 3, kc + 2); CP_WAIT2(); }
        else if (kc + 1 < NK) { CP_WAIT1(); }
        else { CP_WAIT0(); }
        __syncthreads();

        uint32_t st = sb + (uint32_t)(kc % 3) * STG;
        #pragma unroll
        for (int kk = 0; kk < 2; kk++) {
            int ks2 = kk * 32;
            uint32_t ah[4][4], al[4][4], bw[2][4];
            #pragma unroll
            for (int mf = 0; mf < 4; mf++) {
                uint32_t off = SWZ32((a_row + mf * 16) * 64 + ks2 + a_cb);
                ldm_x4(ah[mf], st + off);
                if (TWO) ldm_x4(al[mf], st + 8192 + off);
            }
            #pragma unroll
            for (int bp = 0; bp < 2; bp++) {
                uint32_t off = SWZ32((b_row + bp * 16) * 64 + ks2 + b_cb);
                ldm_x4(bw[bp], st + O_WH + off);
            }
            #pragma unroll
            for (int mf = 0; mf < 4; mf++)
                #pragma unroll
                for (int nf = 0; nf < 4; nf++)
                    mma_f16(acc[mf][nf], ah[mf], &bw[nf >> 1][(nf & 1) * 2]);
            if (TWO) {
                #pragma unroll
                for (int mf = 0; mf < 4; mf++)
                    #pragma unroll
                    for (int nf = 0; nf < 4; nf++)
                        mma_f16(acc[mf][nf], al[mf], &bw[nf >> 1][(nf & 1) * 2]);
            }
        }
    }

    int er = l >> 2, ec = (l & 3) * 2;
    #pragma unroll
    for (int mf = 0; mf < 4; mf++) {
        #pragma unroll
        for (int nf = 0; nf < 4; nf++) {
            int gm = m0 + wm * 64 + mf * 16 + er;
            int gn = n0 + wn * 32 + nf * 8 + ec;
            if (Cf32) {
                float b0 = bias ? bias[gn] : 0.0f;
                float b1 = bias ? bias[gn + 1] : 0.0f;
                float2 v0, v1;
                v0.x = acc[mf][nf][0] + b0; v0.y = acc[mf][nf][1] + b1;
                v1.x = acc[mf][nf][2] + b0; v1.y = acc[mf][nf][3] + b1;
                *(float2*)&Cf32[(size_t)gm * N + gn]       = v0;
                *(float2*)&Cf32[(size_t)(gm + 8) * N + gn] = v1;
            } else {
                #pragma unroll
                for (int rr = 0; rr < 2; rr++) {
                    float vx = acc[mf][nf][rr * 2], vy = acc[mf][nf][rr * 2 + 1];
                    size_t o = (size_t)(gm + rr * 8) * N + gn;
                    *(uint32_t*)&Chi[o] = pack_h2(vx, vy);
                    if (Clo) {
                        float hx = __half2float(__float2half_rn(vx));
                        float hy = __half2float(__float2half_rn(vy));
                        *(uint32_t*)&Clo[o] = pack_h2(vx - hx, vy - hy);
                    }
                }
            }
        }
    }
}

// z = 0..2: Q/K/V projections (1-term, hi-only everywhere).
// z = 3: mask bit-packing hidden under the GEMM.
__global__ __launch_bounds__(256, 2) void qkv_gemm(
    const int* __restrict__ mask, uint32_t* __restrict__ bits)
{
    extern __shared__ char sm[];
    int z = blockIdx.z;
    if (z == 0)
        gemm_body<false>(g_q_hi, nullptr, g_wq_hi, nullptr, nullptr, g_qp_hi, nullptr, sm);
    else if (z == 1)
        gemm_body<false>(g_k_hi, nullptr, g_wk_hi, nullptr, nullptr, g_kp_hi, nullptr, sm);
    else if (z == 2)
        gemm_body<false>(g_v_hi, nullptr, g_wv_hi, nullptr, nullptr, g_vp_hi, nullptr, sm);
    else {
        int flat = (blockIdx.y * gridDim.x + blockIdx.x) * 256 + threadIdx.x;
        #pragma unroll
        for (int t = 0; t < 2; t++) {
            int wdx = flat * 2 + t;
            const int* p = mask + (size_t)wdx * 32;
            uint32_t word = 0;
            #pragma unroll
            for (int j = 0; j < 8; j++) {
                int4 mv = ((const int4*)p)[j];
                word |= (mv.x ? 1u : 0u) << (j * 4 + 0);
                word |= (mv.y ? 1u : 0u) << (j * 4 + 1);
                word |= (mv.z ? 1u : 0u) << (j * 4 + 2);
                word |= (mv.w ? 1u : 0u) << (j * 4 + 3);
            }
            bits[wdx] = word;
        }
    }
}

// Output projection keeps the 2-term split (ctx hi+lo) as precision safety.
__global__ __launch_bounds__(256, 2) void out_gemm(const float* __restrict__ bias,
                                                   float* __restrict__ out)
{
    extern __shared__ char sm[];
    gemm_body<true>(g_c_hi, g_c_lo, g_wd_hi, bias, out, nullptr, nullptr, sm);
}

// ---------------------------------------------------------------------------
// Attention pass 1 (SUM ONLY, Qh*Kh): 64-row CTAs, 64-key double-buffered
// K-hi tiles, 4 CTAs/SM. Scores computed identically to pass 2 -> exact norm.
// ---------------------------------------------------------------------------
#define P1_SMEM (8192 + 16384 + 512)

__global__ __launch_bounds__(256, 4) void attn_pass1()
{
    extern __shared__ char sm[];
    const uint32_t O_Q = 0, O_K = 8192, O_MS = 24576;

    int tid = threadIdx.x, w = tid >> 5, l = tid & 31;
    int bh = blockIdx.y, b = bh >> 4, h = bh & 15;
    int m0 = blockIdx.x * 64;
    int wm = w & 3, wn = w >> 2;
    uint32_t sb = smem_u32(sm);
    float* sm_s = (float*)(sm + O_MS);

    const __half* Qh = g_qp_hi + (size_t)b * SEQ * DM + h * HD;
    const __half* Kh = g_kp_hi + (size_t)b * SEQ * DM + h * HD;
    const uint32_t* mrow_bits = g_mbits + ((size_t)b * SEQ) * 32;

    auto load_k = [&](int nt) {
        uint32_t base = sb + O_K + (uint32_t)(nt & 1) * 8192;
        #pragma unroll
        for (int it = 0; it < 2; it++) {
            int idx = tid + it * 256;
            int row = idx >> 3, c = idx & 7;
            uint32_t so = SWZ(row * 128 + c * 16);
            CP16(base + so, Kh + (size_t)(nt * 64 + row) * DM + c * 8);
        }
        CP_COMMIT();
    };

    #pragma unroll
    for (int it = 0; it < 2; it++) {
        int idx = tid + it * 256;
        int row = idx >> 3, c = idx & 7;
        uint32_t so = SWZ(row * 128 + c * 16);
        *(uint4*)(sm + O_Q + so) =
            *(const uint4*)(Qh + (size_t)(m0 + row) * DM + c * 8);
    }
    load_k(0);

    float srun[2] = {};
    const float scale = 0.03125f;
    int er = l >> 2, ec = (l & 3) * 2;

    for (int nt = 0; nt < 16; nt++) {
        if (nt + 1 < 16) { load_k(nt + 1); CP_WAIT1(); }
        else             { CP_WAIT0(); }
        __syncthreads();

        uint32_t kst = sb + O_K + (uint32_t)(nt & 1) * 8192;

        float acc[4][4] = {};
        #pragma unroll
        for (int kk = 0; kk < 4; kk++) {
            int ks2 = kk * 32;
            uint32_t ah[4], bwh[2][4];
            {
                uint32_t off = SWZ((wm * 16 + (l & 15)) * 128 + ks2 + (l >> 4) * 16);
                ldm_x4(ah, sb + O_Q + off);
            }
            #pragma unroll
            for (int bp = 0; bp < 2; bp++) {
                uint32_t off = SWZ((wn * 32 + bp * 16 + (l & 7) + ((l >> 4) * 8)) * 128
                                   + ks2 + ((l >> 3) & 1) * 16);
                ldm_x4(bwh[bp], kst + off);
            }
            #pragma unroll
            for (int nf = 0; nf < 4; nf++)
                mma_f16(acc[nf], ah, &bwh[nf >> 1][(nf & 1) * 2]);
        }

        #pragma unroll
        for (int rr = 0; rr < 2; rr++) {
            int rl = wm * 16 + rr * 8 + er;
            uint32_t word = mrow_bits[(size_t)(m0 + rl) * 32 + nt * 2 + wn];
            float ts = 0.0f;
            #pragma unroll
            for (int nf = 0; nf < 4; nf++) {
                int sh = nf * 8 + ec;
                float m0f = ((word >> sh) & 1u) ? -1e9f : 0.0f;
                float m1f = ((word >> (sh + 1)) & 1u) ? -1e9f : 0.0f;
                ts += __expf(acc[nf][rr * 2]     * scale + m0f);
                ts += __expf(acc[nf][rr * 2 + 1] * scale + m1f);
            }
            ts += __shfl_xor_sync(0xffffffffu, ts, 1);
            ts += __shfl_xor_sync(0xffffffffu, ts, 2);
            srun[rr] += ts;
        }
        __syncthreads();
    }

    if ((l & 3) == 0) {
        #pragma unroll
        for (int rr = 0; rr < 2; rr++) {
            int rl = wm * 16 + rr * 8 + er;
            sm_s[wn * 64 + rl] = srun[rr];
        }
    }
    __syncthreads();
    if (tid < 64)
        g_rsum[(size_t)bh * SEQ + m0 + tid] = sm_s[tid] + sm_s[64 + tid];
}

// ---------------------------------------------------------------------------
// Attention pass 2: 1-term fp16 (Qh*Kh, Ph*Vh). 64-row CTAs, 64-key
// double-buffered tiles. smem: Qh 8K | KV 2x16K = 40K; 2 CTAs/SM.
// ctx written hi+lo (feeds 2-term out_gemm).
// ---------------------------------------------------------------------------
#define P2_SMEM (8192 + 32768)

__global__ __launch_bounds__(256, 2) void attn_pass2(float* __restrict__ attn)
{
    extern __shared__ char sm[];
    const uint32_t O_Q = 0, O_KV = 8192;

    int tid = threadIdx.x, w = tid >> 5, l = tid & 31;
    int bh = blockIdx.y, b = bh >> 4, h = bh & 15;
    int m0 = blockIdx.x * 64;
    int wm = w & 3, wn = w >> 2;
    uint32_t sb = smem_u32(sm);

    const __half* Qh = g_qp_hi + (size_t)b * SEQ * DM + h * HD;
    const __half* Kh = g_kp_hi + (size_t)b * SEQ * DM + h * HD;
    const __half* Vh = g_vp_hi + (size_t)b * SEQ * DM + h * HD;
    const uint32_t* mrow_bits = g_mbits + ((size_t)b * SEQ) * 32;

    auto load_kv = [&](int nt) {
        uint32_t base = sb + O_KV + (uint32_t)(nt & 1) * 16384;
        #pragma unroll
        for (int it = 0; it < 2; it++) {
            int idx = tid + it * 256;
            int row = idx >> 3, c = idx & 7;
            uint32_t so = SWZ(row * 128 + c * 16);
            size_t g = (size_t)(nt * 64 + row) * DM + c * 8;
            CP16(base + so,        Kh + g);
            CP16(base + 8192 + so, Vh + g);
        }
        CP_COMMIT();
    };

    #pragma unroll
    for (int it = 0; it < 2; it++) {
        int idx = tid + it * 256;
        int row = idx >> 3, c = idx & 7;
        uint32_t so = SWZ(row * 128 + c * 16);
        *(uint4*)(sm + O_Q + so) =
            *(const uint4*)(Qh + (size_t)(m0 + row) * DM + c * 8);
    }
    load_kv(0);

    int er = l >> 2, ec = (l & 3) * 2;
    const float scale = 0.03125f;

    float rinv[2];
    #pragma unroll
    for (int rr = 0; rr < 2; rr++) {
        int gm = m0 + wm * 16 + rr * 8 + er;
        rinv[rr] = __frcp_rn(g_rsum[(size_t)bh * SEQ + gm]);
    }

    float ctx[8][4] = {};

    for (int nt = 0; nt < 16; nt++) {
        if (nt + 1 < 16) { load_kv(nt + 1); CP_WAIT1(); }
        else             { CP_WAIT0(); }
        __syncthreads();

        uint32_t kst = sb + O_KV + (uint32_t)(nt & 1) * 16384;

        float acc[4][4] = {};
        #pragma unroll
        for (int kk = 0; kk < 4; kk++) {
            int ks2 = kk * 32;
            uint32_t ah[4], bwh[2][4];
            {
                uint32_t off = SWZ((wm * 16 + (l & 15)) * 128 + ks2 + (l >> 4) * 16);
                ldm_x4(ah, sb + O_Q + off);
            }
            #pragma unroll
            for (int bp = 0; bp < 2; bp++) {
                uint32_t off = SWZ((wn * 32 + bp * 16 + (l & 7) + ((l >> 4) * 8)) * 128
                                   + ks2 + ((l >> 3) & 1) * 16);
                ldm_x4(bwh[bp], kst + off);
            }
            #pragma unroll
            for (int nf = 0; nf < 4; nf++)
                mma_f16(acc[nf], ah, &bwh[nf >> 1][(nf & 1) * 2]);
        }

        // P = exp(s) * rinv; write attn; keep P in acc
        #pragma unroll
        for (int rr = 0; rr < 2; rr++) {
            int rl = wm * 16 + rr * 8 + er;
            int gm = m0 + rl;
            uint32_t word = mrow_bits[(size_t)gm * 32 + nt * 2 + wn];
            #pragma unroll
            for (int nf = 0; nf < 4; nf++) {
                int sh = nf * 8 + ec;
                float m0f = ((word >> sh) & 1u) ? -1e9f : 0.0f;
                float m1f = ((word >> (sh + 1)) & 1u) ? -1e9f : 0.0f;
                float2 pv;
                pv.x = __expf(acc[nf][rr * 2]     * scale + m0f) * rinv[rr];
                pv.y = __expf(acc[nf][rr * 2 + 1] * scale + m1f) * rinv[rr];
                int gn = nt * 64 + wn * 32 + nf * 8 + ec;
                *(float2*)&attn[((size_t)bh * SEQ + gm) * SEQ + gn] = pv;
                acc[nf][rr * 2]     = pv.x;
                acc[nf][rr * 2 + 1] = pv.y;
            }
        }

        // ctx += Ph @ Vh (hi-only P)
        #pragma unroll
        for (int kk = 0; kk < 2; kk++) {
            uint32_t pah[4], bvh[4][4];
            {
                float* a0 = acc[kk * 2];
                float* a1 = acc[kk * 2 + 1];
                pah[0] = pack_h2(a0[0], a0[1]);
                pah[1] = pack_h2(a0[2], a0[3]);
                pah[2] = pack_h2(a1[0], a1[1]);
                pah[3] = pack_h2(a1[2], a1[3]);
            }
            #pragma unroll
            for (int nb = 0; nb < 4; nb++) {
                uint32_t off = SWZ((wn * 32 + kk * 16 + (l & 15)) * 128
                                   + (nb * 16 + (l >> 4) * 8) * 2);
                ldm_x4t(bvh[nb], kst + 8192 + off);
            }
            #pragma unroll
            for (int nd = 0; nd < 8; nd++)
                mma_f16(ctx[nd], pah, &bvh[nd >> 1][(nd & 1) * 2]);
        }
        __syncthreads();
    }

    // cross-wn reduce via smem (alias KV), write ctx fp16 hi+lo
    float* red = (float*)(sm + O_KV);   // 64 x 64 fp32 = 16KB
    if (wn == 1) {
        #pragma unroll
        for (int nd = 0; nd < 8; nd++)
            #pragma unroll
            for (int rr = 0; rr < 2; rr++) {
                int row = wm * 16 + rr * 8 + er;
                float2 v;
                v.x = ctx[nd][rr * 2];
                v.y = ctx[nd][rr * 2 + 1];
                *(float2*)&red[row * 64 + nd * 8 + ec] = v;
            }
    }
    __syncthreads();
    if (wn == 0) {
        __half* Chi = g_c_hi + (size_t)b * SEQ * DM + h * HD;
        __half* Clo = g_c_lo + (size_t)b * SEQ * DM + h * HD;
        #pragma unroll
        for (int nd = 0; nd < 8; nd++)
            #pragma unroll
            for (int rr = 0; rr < 2; rr++) {
                int row = wm * 16 + rr * 8 + er;
                int col = nd * 8 + ec;
                float2 o = *(float2*)&red[row * 64 + col];
                float vx = ctx[nd][rr * 2] + o.x;
                float vy = ctx[nd][rr * 2 + 1] + o.y;
                float hx = __half2float(__float2half_rn(vx));
                float hy = __half2float(__float2half_rn(vy));
                size_t off = (size_t)(m0 + row) * DM + col;
                *(uint32_t*)&Chi[off] = pack_h2(vx, vy);
                *(uint32_t*)&Clo[off] = pack_h2(vx - hx, vy - hy);
            }
    }
}

// ---------------------------------------------------------------------------
extern "C" void kernel_launch(void* const* d_in, const int* in_sizes, int n_in,
                              void* d_out, int out_size)
{
    const float* q   = (const float*)d_in[0];
    const float* k   = (const float*)d_in[1];
    const float* v   = (const float*)d_in[2];
    const int*  mask = (const int*)d_in[3];
    const float* Wq  = (const float*)d_in[4];
    const float* Wk  = (const float*)d_in[5];
    const float* Wv  = (const float*)d_in[6];
    const float* Wd  = (const float*)d_in[7];
    const float* bd  = (const float*)d_in[8];
    float* out = (float*)d_out;

    const long long out_elems  = (long long)BQ * SEQ * DM;
    const long long attn_elems = (long long)BQ * NH * SEQ * SEQ;
    float* attn;
    if ((long long)out_size >= out_elems + attn_elems) {
        attn = out + out_elems;
    } else {
        cudaGetSymbolAddress((void**)&attn, g_attn);
    }

    cudaFuncSetAttribute(qkv_gemm,   cudaFuncAttributeMaxDynamicSharedMemorySize, GEMM_SMEM1);
    cudaFuncSetAttribute(out_gemm,   cudaFuncAttributeMaxDynamicSharedMemorySize, GEMM_SMEM2);
    cudaFuncSetAttribute(attn_pass1, cudaFuncAttributeMaxDynamicSharedMemorySize, P1_SMEM);
    cudaFuncSetAttribute(attn_pass2, cudaFuncAttributeMaxDynamicSharedMemorySize, P2_SMEM);

    uint32_t* mb;
    cudaGetSymbolAddress((void**)&mb, g_mbits);

    prep<<<16384, 256>>>(q, k, v, Wq, Wk, Wv, Wd);

    // z=0..2: projections; z=3: mask packing hidden under GEMM
    qkv_gemm<<<dim3(DM / 128, (BQ * SEQ) / 128, 4), 256, GEMM_SMEM1>>>(mask, mb);

    dim3 ga(SEQ / 64, BQ * NH);   // 16 x 64 = 1024 CTAs
    attn_pass1<<<ga, 256, P1_SMEM>>>();
    attn_pass2<<<ga, 256, P2_SMEM>>>(attn);

    out_gemm<<<dim3(DM / 128, (BQ * SEQ) / 128), 256, GEMM_SMEM2>>>(bd, out);
}